// round 10
// baseline (speedup 1.0000x reference)
#include <cuda_runtime.h>
#include <cuda_bf16.h>
#include <math.h>
#include <stdint.h>

typedef __nv_bfloat16 bf16;

// ---------------- scratch ----------------
__device__ float g_hT[2][16384];
__device__ float g_cT[16384];
__device__ float g_hseq[512 * 1024];
__device__ float g_gx[2 * 512 * 2048];
__device__ float g_hemA[512 * 512];
__device__ float g_xt[4096 * 512];
__device__ float g_sc[512 * 256];
__device__ float g_alpha[512 * 256];
__device__ bf16 g_col2[4096u * 9216u];          // [hi(4608) | lo(4608)]
__device__ bf16 g_wem2[512 * 9216];
__device__ bf16 g_en2[512 * 1024];
__device__ bf16 g_wihf2[2048 * 1024], g_wihb2[2048 * 1024];
__device__ bf16 g_wdec2[512 * 2048];
__device__ bf16 g_whem2[512 * 1024];
__device__ bf16 g_hseq2[512 * 2048];
__device__ bf16 g_hde2[512 * 1024];

// ---------------- helpers ----------------
__device__ __forceinline__ void fma2(unsigned long long& d, unsigned long long a, unsigned long long b) {
    asm("fma.rn.f32x2 %0, %1, %2, %0;" : "+l"(d) : "l"(a), "l"(b));
}
__device__ __forceinline__ unsigned long long pk(float lo, float hi) {
    unsigned long long r;
    asm("mov.b64 %0, {%1, %2};" : "=l"(r) : "f"(lo), "f"(hi));
    return r;
}
__device__ __forceinline__ float2 upk(unsigned long long v) {
    float2 f;
    asm("mov.b64 {%0, %1}, %2;" : "=f"(f.x), "=f"(f.y) : "l"(v));
    return f;
}
__device__ __forceinline__ float tanh_fast(float x) {
    float y;
    asm("tanh.approx.f32 %0, %1;" : "=f"(y) : "f"(x));
    return y;
}
__device__ __forceinline__ uint32_t smem_u32(const void* p) {
    uint32_t a;
    asm("{ .reg .u64 t; cvta.to.shared.u64 t, %1; cvt.u32.u64 %0, t; }" : "=r"(a) : "l"(p));
    return a;
}

// ---------------- init & converts ----------------
__global__ void k_zero() {
    int i = blockIdx.x * 256 + threadIdx.x;
    g_hT[0][i] = 0.f;
    g_cT[i] = 0.f;
}
__global__ void k_cvt2(const float* __restrict__ s, bf16* __restrict__ d, int K, int n) {
    int i = blockIdx.x * 256 + threadIdx.x;
    if (i >= n) return;
    int m = i / K, k = i % K;
    float v = s[i];
    bf16 h = __float2bfloat16(v);
    bf16 l = __float2bfloat16(v - __bfloat162float(h));
    size_t base = (size_t)m * 2 * K;
    d[base + k] = h;
    d[base + K + k] = l;
}
__global__ void k_im2col2(const float* __restrict__ cf) {
    int idx = blockIdx.x * 256 + threadIdx.x;   // < 4096*4608
    int k = idx % 4608, m = idx / 4608;
    int kw = k % 3, kh = (k / 3) % 3, c = k / 9;
    int w = m & 31, h = (m >> 5) & 7, b = m >> 8;
    int ih = h + kh - 1, iw = w + kw - 1;
    float v = 0.f;
    if (ih >= 0 && ih < 8 && iw >= 0 && iw < 32) v = cf[((b * 512 + c) * 8 + ih) * 32 + iw];
    bf16 hv = __float2bfloat16(v);
    size_t base = (size_t)m * 9216;
    g_col2[base + k] = hv;
    g_col2[base + 4608 + k] = __float2bfloat16(v - __bfloat162float(hv));
}

// ---------------- HMMA bf16 NT GEMM, cp.async double-buffered (validated R8) ----
#define PAD 40
#define TSZ (128 * PAD)
__device__ __forceinline__ void ld_chunk(uint32_t ds, const bf16* __restrict__ src,
                                         int row0, int rs, int koff, int tid) {
#pragma unroll
    for (int j = 0; j < 2; j++) {
        int ch = tid + (j << 8);
        int row = ch >> 2, c = ch & 3;
        const void* g = src + (size_t)(row0 + row) * rs + koff + (c << 3);
        uint32_t d = ds + (row * PAD + (c << 3)) * 2;
        asm volatile("cp.async.ca.shared.global [%0], [%1], 16;" :: "r"(d), "l"(g) : "memory");
    }
}

__global__ __launch_bounds__(256) void k_mma_gemm(
    const bf16* __restrict__ A2, const bf16* __restrict__ B2,
    const float* __restrict__ bias, const float* __restrict__ bias2,
    float* __restrict__ Cf, bf16* __restrict__ C2, int C2K,
    float* __restrict__ Cscat, int N, int K)
{
    __shared__ __align__(16) bf16 As[2][TSZ];
    __shared__ __align__(16) bf16 Bs[2][TSZ];
    int tid = threadIdx.x, lane = tid & 31, wid = tid >> 5;
    int g = lane >> 2, t2 = (lane & 3) << 1;
    int bm = blockIdx.y << 7, bn = blockIdx.x << 7;
    int wm = (wid >> 1) << 5, wn = (wid & 1) << 6;
    uint32_t asb = smem_u32(As), bsb = smem_u32(Bs);
    int rs = K << 1;
    int KC = K >> 5, S = KC * 3;
    float acc[2][8][4];
#pragma unroll
    for (int mt = 0; mt < 2; mt++)
#pragma unroll
        for (int nt = 0; nt < 8; nt++)
#pragma unroll
            for (int q = 0; q < 4; q++) acc[mt][nt][q] = 0.f;

    ld_chunk(asb, A2, bm, rs, 0, tid);
    ld_chunk(bsb, B2, bn, rs, 0, tid);
    asm volatile("cp.async.commit_group;" ::: "memory");

    for (int s = 0; s < S; s++) {
        int cur = s & 1;
        if (s + 1 < S) {
            int s1 = s + 1;
            int p = s1 / KC, cc = s1 - p * KC;
            int aoff = ((p == 2) ? K : 0) + (cc << 5);
            int boff = ((p == 1) ? K : 0) + (cc << 5);
            uint32_t nb = (uint32_t)((cur ^ 1) * TSZ * 2);
            ld_chunk(asb + nb, A2, bm, rs, aoff, tid);
            ld_chunk(bsb + nb, B2, bn, rs, boff, tid);
            asm volatile("cp.async.commit_group;" ::: "memory");
            asm volatile("cp.async.wait_group 1;" ::: "memory");
        } else {
            asm volatile("cp.async.wait_group 0;" ::: "memory");
        }
        __syncthreads();
        const bf16* Asc = As[cur];
        const bf16* Bsc = Bs[cur];
#pragma unroll
        for (int kk = 0; kk < 2; kk++) {
            int kb = kk << 4;
            uint32_t a[2][4], b[8][2];
#pragma unroll
            for (int mt = 0; mt < 2; mt++) {
                const bf16* ab = &Asc[(wm + (mt << 4) + g) * PAD + kb + t2];
                a[mt][0] = *(const uint32_t*)ab;
                a[mt][1] = *(const uint32_t*)(ab + 8 * PAD);
                a[mt][2] = *(const uint32_t*)(ab + 8);
                a[mt][3] = *(const uint32_t*)(ab + 8 * PAD + 8);
            }
#pragma unroll
            for (int nt = 0; nt < 8; nt++) {
                const bf16* bb = &Bsc[(wn + (nt << 3) + g) * PAD + kb + t2];
                b[nt][0] = *(const uint32_t*)bb;
                b[nt][1] = *(const uint32_t*)(bb + 8);
            }
#pragma unroll
            for (int mt = 0; mt < 2; mt++)
#pragma unroll
                for (int nt = 0; nt < 8; nt++)
                    asm volatile(
                        "mma.sync.aligned.m16n8k16.row.col.f32.bf16.bf16.f32 "
                        "{%0,%1,%2,%3},{%4,%5,%6,%7},{%8,%9},{%0,%1,%2,%3};"
                        : "+f"(acc[mt][nt][0]), "+f"(acc[mt][nt][1]),
                          "+f"(acc[mt][nt][2]), "+f"(acc[mt][nt][3])
                        : "r"(a[mt][0]), "r"(a[mt][1]), "r"(a[mt][2]), "r"(a[mt][3]),
                          "r"(b[nt][0]), "r"(b[nt][1]));
        }
        __syncthreads();
    }
#pragma unroll
    for (int mt = 0; mt < 2; mt++)
#pragma unroll
        for (int nt = 0; nt < 8; nt++) {
            int r0 = bm + wm + (mt << 4) + g;
            int c0 = bn + wn + (nt << 3) + t2;
            float bv0 = bias[c0] + (bias2 ? bias2[c0] : 0.f);
            float bv1 = bias[c0 + 1] + (bias2 ? bias2[c0 + 1] : 0.f);
            float v[4] = {acc[mt][nt][0] + bv0, acc[mt][nt][1] + bv1,
                          acc[mt][nt][2] + bv0, acc[mt][nt][3] + bv1};
            int rr[4] = {r0, r0, r0 + 8, r0 + 8};
            int cc[4] = {c0, c0 + 1, c0, c0 + 1};
#pragma unroll
            for (int q = 0; q < 4; q++) {
                int m = rr[q], n = cc[q];
                float x = v[q];
                if (Cf) Cf[(size_t)m * N + n] = x;
                if (C2) {
                    bf16 h = __float2bfloat16(x);
                    size_t base = (size_t)m * 2 * C2K;
                    C2[base + n] = h;
                    C2[base + C2K + n] = __float2bfloat16(x - __bfloat162float(h));
                }
                if (Cscat) {
                    int t = m >> 4, bb_ = m & 15;
                    Cscat[((bb_ << 5) + t) * 1024 + n] = x;
                }
            }
        }
}

// ---------------- LSTM step (validated) ----------------
__global__ __launch_bounds__(256) void k_lstm_step(
    const float* __restrict__ Whh_f, const float* __restrict__ Whh_b, int s)
{
    __shared__ float sbuf[8192];
    int dir = blockIdx.x & 1;
    int h0 = (blockIdx.x >> 1) << 5;
    int t = dir ? (31 - s) : s;
    const float* __restrict__ Whh = dir ? Whh_b : Whh_f;
    int tid = threadIdx.x;
    {
        const float4* hp4 = (const float4*)(g_hT[s & 1] + dir * 8192);
        float4* sb4 = (float4*)sbuf;
#pragma unroll
        for (int i = 0; i < 8; i++) sb4[tid + i * 256] = hp4[tid + i * 256];
    }
    __syncthreads();
    int kq = tid >> 6;
    int sub = tid & 63;
    int gate = sub >> 4;
    int hg = sub & 15;
    int h = h0 + (hg << 1);
    const float* wr0 = Whh + (size_t)(gate * 512 + h) * 512 + (kq << 7);
    const float* wr1 = wr0 + 512;
    unsigned long long acc[2][8];
#pragma unroll
    for (int p = 0; p < 2; p++)
#pragma unroll
        for (int j = 0; j < 8; j++) acc[p][j] = 0ull;

    for (int k4 = 0; k4 < 128; k4 += 4) {
        float4 wa = *(const float4*)(wr0 + k4);
        float4 wb = *(const float4*)(wr1 + k4);
        float wav[4] = {wa.x, wa.y, wa.z, wa.w};
        float wbv[4] = {wb.x, wb.y, wb.z, wb.w};
#pragma unroll
        for (int j = 0; j < 4; j++) {
            int k = (kq << 7) + k4 + j;
            unsigned long long w2a = pk(wav[j], wav[j]);
            unsigned long long w2b = pk(wbv[j], wbv[j]);
            const ulonglong2* hb = (const ulonglong2*)&sbuf[k << 4];
            ulonglong2 q0 = hb[0], q1 = hb[1], q2 = hb[2], q3 = hb[3];
            fma2(acc[0][0], w2a, q0.x); fma2(acc[0][1], w2a, q0.y);
            fma2(acc[0][2], w2a, q1.x); fma2(acc[0][3], w2a, q1.y);
            fma2(acc[0][4], w2a, q2.x); fma2(acc[0][5], w2a, q2.y);
            fma2(acc[0][6], w2a, q3.x); fma2(acc[0][7], w2a, q3.y);
            fma2(acc[1][0], w2b, q0.x); fma2(acc[1][1], w2b, q0.y);
            fma2(acc[1][2], w2b, q1.x); fma2(acc[1][3], w2b, q1.y);
            fma2(acc[1][4], w2b, q2.x); fma2(acc[1][5], w2b, q2.y);
            fma2(acc[1][6], w2b, q3.x); fma2(acc[1][7], w2b, q3.y);
        }
    }
    __syncthreads();
#pragma unroll
    for (int p = 0; p < 2; p++)
#pragma unroll
        for (int j = 0; j < 8; j++) {
            float2 v = upk(acc[p][j]);
            int base = ((((kq << 2) + gate) * 16 + hg) * 2 + p) * 16 + (j << 1);
            sbuf[base] = v.x;
            sbuf[base + 1] = v.y;
        }
    __syncthreads();
    const float* gx = g_gx + ((size_t)dir * 512 + t * 16) * 2048;
    float* hNext = g_hT[(s + 1) & 1];
    for (int it = tid; it < 512; it += 256) {
        int hloc = it >> 4, b = it & 15;
        int hgl = hloc >> 1, p = hloc & 1;
        float v[4];
#pragma unroll
        for (int g2 = 0; g2 < 4; g2++) {
            int bi = ((g2 * 16 + hgl) * 2 + p) * 16 + b;
            v[g2] = sbuf[bi] + sbuf[bi + 2048] + sbuf[bi + 4096] + sbuf[bi + 6144]
                  + gx[(size_t)b * 2048 + g2 * 512 + h0 + hloc];
        }
        float i_ = 1.f / (1.f + expf(-v[0]));
        float f_ = 1.f / (1.f + expf(-v[1]));
        float gg = tanhf(v[2]);
        float o_ = 1.f / (1.f + expf(-v[3]));
        int hh = h0 + hloc;
        int ci = dir * 8192 + hh * 16 + b;
        float c = f_ * g_cT[ci] + i_ * gg;
        g_cT[ci] = c;
        float hn = o_ * tanhf(c);
        hNext[ci] = hn;
        g_hseq[(t * 16 + b) * 1024 + dir * 512 + hh] = hn;
    }
}

// ---------------- attention: scores with 8-t x reuse ----------------
__global__ __launch_bounds__(256) void k_att_scores(
    const float* __restrict__ w_att, const float* __restrict__ b_att)
{
    __shared__ float hm[8][512];
    __shared__ float wv[512];
    int b = blockIdx.x & 15, tg = blockIdx.x >> 4;   // tg 0..3
    int tid = threadIdx.x;
    wv[tid] = w_att[tid];
    wv[tid + 256] = w_att[tid + 256];
#pragma unroll
    for (int t8 = 0; t8 < 8; t8++) {
        int row = (tg * 8 + t8) * 16 + b;
        hm[t8][tid] = g_hemA[row * 512 + tid];
        hm[t8][tid + 256] = g_hemA[row * 512 + tid + 256];
    }
    __syncthreads();
    int lane = tid & 31, wrp = tid >> 5;
    float batt = b_att[0];
    const float* xb = g_xt + (size_t)b * 256 * 512;
    for (int hw = wrp; hw < 256; hw += 8) {
        const float* xr = xb + hw * 512;
        float s[8] = {0.f, 0.f, 0.f, 0.f, 0.f, 0.f, 0.f, 0.f};
        for (int e = lane; e < 512; e += 32) {
            float xv = xr[e], we = wv[e];
#pragma unroll
            for (int t8 = 0; t8 < 8; t8++) s[t8] += we * tanh_fast(xv + hm[t8][e]);
        }
#pragma unroll
        for (int o = 16; o; o >>= 1)
#pragma unroll
            for (int t8 = 0; t8 < 8; t8++) s[t8] += __shfl_xor_sync(0xffffffffu, s[t8], o);
        if (lane == 0)
#pragma unroll
            for (int t8 = 0; t8 < 8; t8++)
                g_sc[((tg * 8 + t8) * 16 + b) * 256 + hw] = s[t8] + batt;
    }
}

// ---------------- attention: softmax per (t,b) row ----------------
__global__ __launch_bounds__(256) void k_att_soft() {
    __shared__ float red[256];
    int r = blockIdx.x;
    int tid = threadIdx.x;
    float sv = g_sc[r * 256 + tid];
    red[tid] = sv;
    __syncthreads();
    for (int st = 128; st; st >>= 1) {
        if (tid < st) red[tid] = fmaxf(red[tid], red[tid + st]);
        __syncthreads();
    }
    float mx = red[0];
    __syncthreads();
    float e = expf(sv - mx);
    red[tid] = e;
    __syncthreads();
    for (int st = 128; st; st >>= 1) {
        if (tid < st) red[tid] += red[tid + st];
        __syncthreads();
    }
    g_alpha[r * 256 + tid] = e / red[0];
}

// ---------------- attention: weighted sum with 8-t x reuse ----------------
__global__ __launch_bounds__(256) void k_att_wsum(float* __restrict__ out) {
    __shared__ float al[8][256];
    int b = blockIdx.x & 15, tg = blockIdx.x >> 4;
    int tid = threadIdx.x;
#pragma unroll
    for (int t8 = 0; t8 < 8; t8++)
        al[t8][tid] = g_alpha[((tg * 8 + t8) * 16 + b) * 256 + tid];
    __syncthreads();
    const float* xb = g_xt + (size_t)b * 256 * 512;
    float a0[8] = {0.f, 0.f, 0.f, 0.f, 0.f, 0.f, 0.f, 0.f};
    float a1[8] = {0.f, 0.f, 0.f, 0.f, 0.f, 0.f, 0.f, 0.f};
    for (int hw = 0; hw < 256; hw++) {
        float x0 = xb[hw * 512 + tid];
        float x1 = xb[hw * 512 + tid + 256];
#pragma unroll
        for (int t8 = 0; t8 < 8; t8++) {
            float av = al[t8][hw];
            a0[t8] += av * x0;
            a1[t8] += av * x1;
        }
    }
#pragma unroll
    for (int t8 = 0; t8 < 8; t8++) {
        float* orow = out + (size_t)((b << 5) + tg * 8 + t8) * 1024 + 512;
        orow[tid] = a0[t8];
        orow[tid + 256] = a1[t8];
    }
}

// ---------------- launch ----------------
extern "C" void kernel_launch(void* const* d_in, const int* in_sizes, int n_in,
                              void* d_out, int out_size) {
    const float* hidden_en = (const float*)d_in[0];
    const float* conv_f = (const float*)d_in[1];
    const float* W_ih_f = (const float*)d_in[2];
    const float* W_hh_f = (const float*)d_in[3];
    const float* b_ih_f = (const float*)d_in[4];
    const float* b_hh_f = (const float*)d_in[5];
    const float* W_ih_b = (const float*)d_in[6];
    const float* W_hh_b = (const float*)d_in[7];
    const float* b_ih_b = (const float*)d_in[8];
    const float* b_hh_b = (const float*)d_in[9];
    const float* W_dec = (const float*)d_in[10];
    const float* b_dec = (const float*)d_in[11];
    const float* W_em = (const float*)d_in[12];
    const float* b_em = (const float*)d_in[13];
    const float* W_hem = (const float*)d_in[14];
    const float* b_hem = (const float*)d_in[15];
    const float* w_att = (const float*)d_in[16];
    const float* b_att = (const float*)d_in[17];
    float* out = (float*)d_out;

#define SYM(p, s) void* p; cudaGetSymbolAddress(&p, s)
    SYM(p_gx, g_gx); SYM(p_xt, g_xt); SYM(p_hseq, g_hseq); SYM(p_hem, g_hemA);
    SYM(p_col2, g_col2); SYM(p_wem2, g_wem2); SYM(p_en2, g_en2);
    SYM(p_wf2, g_wihf2); SYM(p_wb2, g_wihb2);
    SYM(p_wd2, g_wdec2); SYM(p_wh2, g_whem2);
    SYM(p_hs2, g_hseq2); SYM(p_hd2, g_hde2);

    // launches 1-5 (so the conv GEMM is launch #6 for ncu -s 5 -c 1)
    k_zero<<<64, 256>>>();
    k_im2col2<<<(4096 * 4608) / 256, 256>>>(conv_f);
    k_cvt2<<<(512 * 4608) / 256, 256>>>(W_em, (bf16*)p_wem2, 4608, 512 * 4608);
    k_cvt2<<<(512 * 512) / 256, 256>>>(hidden_en, (bf16*)p_en2, 512, 512 * 512);
    k_cvt2<<<(2048 * 512) / 256, 256>>>(W_ih_f, (bf16*)p_wf2, 512, 2048 * 512);
    // launch 6: conv GEMM -> g_xt (M=4096, N=512, K=4608)
    k_mma_gemm<<<dim3(4, 32), 256>>>((bf16*)p_col2, (bf16*)p_wem2, b_em, nullptr,
                                     (float*)p_xt, nullptr, 0, nullptr, 512, 4608);
    // remaining converts
    k_cvt2<<<(2048 * 512) / 256, 256>>>(W_ih_b, (bf16*)p_wb2, 512, 2048 * 512);
    k_cvt2<<<(512 * 1024) / 256, 256>>>(W_dec, (bf16*)p_wd2, 1024, 512 * 1024);
    k_cvt2<<<(512 * 512) / 256, 256>>>(W_hem, (bf16*)p_wh2, 512, 512 * 512);

    // input projections (M=512, N=2048, K=512)
    k_mma_gemm<<<dim3(16, 4), 256>>>((bf16*)p_en2, (bf16*)p_wf2, b_ih_f, b_hh_f,
                                     (float*)p_gx, nullptr, 0, nullptr, 2048, 512);
    k_mma_gemm<<<dim3(16, 4), 256>>>((bf16*)p_en2, (bf16*)p_wb2, b_ih_b, b_hh_b,
                                     (float*)p_gx + 512 * 2048, nullptr, 0, nullptr, 2048, 512);

    for (int s = 0; s < 32; s++) k_lstm_step<<<32, 256>>>(W_hh_f, W_hh_b, s);

    k_cvt2<<<(512 * 1024) / 256, 256>>>((float*)p_hseq, (bf16*)p_hs2, 1024, 512 * 1024);
    // dec (M=512, N=512, K=1024): scatter hidden_de into out + [hi|lo] hde
    k_mma_gemm<<<dim3(4, 4), 256>>>((bf16*)p_hs2, (bf16*)p_wd2, b_dec, nullptr,
                                    nullptr, (bf16*)p_hd2, 512, out, 512, 1024);
    // hem (M=512, N=512, K=512)
    k_mma_gemm<<<dim3(4, 4), 256>>>((bf16*)p_hd2, (bf16*)p_wh2, b_hem, nullptr,
                                    (float*)p_hem, nullptr, 0, nullptr, 512, 512);

    // attention
    k_att_scores<<<64, 256>>>(w_att, b_att);
    k_att_soft<<<512, 256>>>();
    k_att_wsum<<<64, 256>>>(out);
}

// round 12
// speedup vs baseline: 1.0659x; 1.0659x over previous
#include <cuda_runtime.h>
#include <cuda_bf16.h>
#include <math.h>
#include <stdint.h>

typedef __nv_bfloat16 bf16;

// ---------------- scratch ----------------
__device__ float g_hT[2][16384];
__device__ float g_cT[16384];
__device__ float g_hseq[512 * 1024];
__device__ float g_gx[2 * 512 * 2048];
__device__ float g_hemA[512 * 512];
__device__ float g_xt[4096 * 512];
__device__ float g_sc[512 * 256];
__device__ float g_alpha[512 * 256];
__device__ bf16 g_col2[4096u * 9216u];          // [hi(4608) | lo(4608)]
__device__ bf16 g_wem2[512 * 9216];
__device__ bf16 g_en2[512 * 1024];
__device__ bf16 g_wihf2[2048 * 1024], g_wihb2[2048 * 1024];
__device__ bf16 g_wdec2[512 * 2048];
__device__ bf16 g_whem2[512 * 1024];
__device__ bf16 g_hseq2[512 * 2048];
__device__ bf16 g_hde2[512 * 1024];

// ---------------- helpers ----------------
__device__ __forceinline__ void fma2(unsigned long long& d, unsigned long long a, unsigned long long b) {
    asm("fma.rn.f32x2 %0, %1, %2, %0;" : "+l"(d) : "l"(a), "l"(b));
}
__device__ __forceinline__ unsigned long long pk(float lo, float hi) {
    unsigned long long r;
    asm("mov.b64 %0, {%1, %2};" : "=l"(r) : "f"(lo), "f"(hi));
    return r;
}
__device__ __forceinline__ float2 upk(unsigned long long v) {
    float2 f;
    asm("mov.b64 {%0, %1}, %2;" : "=f"(f.x), "=f"(f.y) : "l"(v));
    return f;
}
__device__ __forceinline__ float tanh_fast(float x) {
    float y;
    asm("tanh.approx.f32 %0, %1;" : "=f"(y) : "f"(x));
    return y;
}
__device__ __forceinline__ uint32_t smem_u32(const void* p) {
    uint32_t a;
    asm("{ .reg .u64 t; cvta.to.shared.u64 t, %1; cvt.u32.u64 %0, t; }" : "=r"(a) : "l"(p));
    return a;
}

// ---------------- init & converts ----------------
__global__ void k_zero() {
    int i = blockIdx.x * 256 + threadIdx.x;
    g_hT[0][i] = 0.f;
    g_cT[i] = 0.f;
}
__global__ void k_cvt2(const float* __restrict__ s, bf16* __restrict__ d, int K, int n) {
    int i = blockIdx.x * 256 + threadIdx.x;
    if (i >= n) return;
    int m = i / K, k = i % K;
    float v = s[i];
    bf16 h = __float2bfloat16(v);
    bf16 l = __float2bfloat16(v - __bfloat162float(h));
    size_t base = (size_t)m * 2 * K;
    d[base + k] = h;
    d[base + K + k] = l;
}
__global__ void k_im2col2(const float* __restrict__ cf) {
    int idx = blockIdx.x * 256 + threadIdx.x;   // < 4096*4608
    int k = idx % 4608, m = idx / 4608;
    int kw = k % 3, kh = (k / 3) % 3, c = k / 9;
    int w = m & 31, h = (m >> 5) & 7, b = m >> 8;
    int ih = h + kh - 1, iw = w + kw - 1;
    float v = 0.f;
    if (ih >= 0 && ih < 8 && iw >= 0 && iw < 32) v = cf[((b * 512 + c) * 8 + ih) * 32 + iw];
    bf16 hv = __float2bfloat16(v);
    size_t base = (size_t)m * 9216;
    g_col2[base + k] = hv;
    g_col2[base + 4608 + k] = __float2bfloat16(v - __bfloat162float(hv));
}

// ---------------- HMMA bf16 NT GEMM, cp.async double-buffered (validated R8) ----
#define PAD 40
#define TSZ (128 * PAD)
__device__ __forceinline__ void ld_chunk(uint32_t ds, const bf16* __restrict__ src,
                                         int row0, int rs, int koff, int tid) {
#pragma unroll
    for (int j = 0; j < 2; j++) {
        int ch = tid + (j << 8);
        int row = ch >> 2, c = ch & 3;
        const void* g = src + (size_t)(row0 + row) * rs + koff + (c << 3);
        uint32_t d = ds + (row * PAD + (c << 3)) * 2;
        asm volatile("cp.async.ca.shared.global [%0], [%1], 16;" :: "r"(d), "l"(g) : "memory");
    }
}

__global__ __launch_bounds__(256) void k_mma_gemm(
    const bf16* __restrict__ A2, const bf16* __restrict__ B2,
    const float* __restrict__ bias, const float* __restrict__ bias2,
    float* __restrict__ Cf, bf16* __restrict__ C2, int C2K,
    float* __restrict__ Cscat, int N, int K)
{
    __shared__ __align__(16) bf16 As[2][TSZ];
    __shared__ __align__(16) bf16 Bs[2][TSZ];
    int tid = threadIdx.x, lane = tid & 31, wid = tid >> 5;
    int g = lane >> 2, t2 = (lane & 3) << 1;
    int bm = blockIdx.y << 7, bn = blockIdx.x << 7;
    int wm = (wid >> 1) << 5, wn = (wid & 1) << 6;
    uint32_t asb = smem_u32(As), bsb = smem_u32(Bs);
    int rs = K << 1;
    int KC = K >> 5, S = KC * 3;
    float acc[2][8][4];
#pragma unroll
    for (int mt = 0; mt < 2; mt++)
#pragma unroll
        for (int nt = 0; nt < 8; nt++)
#pragma unroll
            for (int q = 0; q < 4; q++) acc[mt][nt][q] = 0.f;

    ld_chunk(asb, A2, bm, rs, 0, tid);
    ld_chunk(bsb, B2, bn, rs, 0, tid);
    asm volatile("cp.async.commit_group;" ::: "memory");

    for (int s = 0; s < S; s++) {
        int cur = s & 1;
        if (s + 1 < S) {
            int s1 = s + 1;
            int p = s1 / KC, cc = s1 - p * KC;
            int aoff = ((p == 2) ? K : 0) + (cc << 5);
            int boff = ((p == 1) ? K : 0) + (cc << 5);
            uint32_t nb = (uint32_t)((cur ^ 1) * TSZ * 2);
            ld_chunk(asb + nb, A2, bm, rs, aoff, tid);
            ld_chunk(bsb + nb, B2, bn, rs, boff, tid);
            asm volatile("cp.async.commit_group;" ::: "memory");
            asm volatile("cp.async.wait_group 1;" ::: "memory");
        } else {
            asm volatile("cp.async.wait_group 0;" ::: "memory");
        }
        __syncthreads();
        const bf16* Asc = As[cur];
        const bf16* Bsc = Bs[cur];
#pragma unroll
        for (int kk = 0; kk < 2; kk++) {
            int kb = kk << 4;
            uint32_t a[2][4], b[8][2];
#pragma unroll
            for (int mt = 0; mt < 2; mt++) {
                const bf16* ab = &Asc[(wm + (mt << 4) + g) * PAD + kb + t2];
                a[mt][0] = *(const uint32_t*)ab;
                a[mt][1] = *(const uint32_t*)(ab + 8 * PAD);
                a[mt][2] = *(const uint32_t*)(ab + 8);
                a[mt][3] = *(const uint32_t*)(ab + 8 * PAD + 8);
            }
#pragma unroll
            for (int nt = 0; nt < 8; nt++) {
                const bf16* bb = &Bsc[(wn + (nt << 3) + g) * PAD + kb + t2];
                b[nt][0] = *(const uint32_t*)bb;
                b[nt][1] = *(const uint32_t*)(bb + 8);
            }
#pragma unroll
            for (int mt = 0; mt < 2; mt++)
#pragma unroll
                for (int nt = 0; nt < 8; nt++)
                    asm volatile(
                        "mma.sync.aligned.m16n8k16.row.col.f32.bf16.bf16.f32 "
                        "{%0,%1,%2,%3},{%4,%5,%6,%7},{%8,%9},{%0,%1,%2,%3};"
                        : "+f"(acc[mt][nt][0]), "+f"(acc[mt][nt][1]),
                          "+f"(acc[mt][nt][2]), "+f"(acc[mt][nt][3])
                        : "r"(a[mt][0]), "r"(a[mt][1]), "r"(a[mt][2]), "r"(a[mt][3]),
                          "r"(b[nt][0]), "r"(b[nt][1]));
        }
        __syncthreads();
    }
#pragma unroll
    for (int mt = 0; mt < 2; mt++)
#pragma unroll
        for (int nt = 0; nt < 8; nt++) {
            int r0 = bm + wm + (mt << 4) + g;
            int c0 = bn + wn + (nt << 3) + t2;
            float bv0 = bias[c0] + (bias2 ? bias2[c0] : 0.f);
            float bv1 = bias[c0 + 1] + (bias2 ? bias2[c0 + 1] : 0.f);
            float v[4] = {acc[mt][nt][0] + bv0, acc[mt][nt][1] + bv1,
                          acc[mt][nt][2] + bv0, acc[mt][nt][3] + bv1};
            int rr[4] = {r0, r0, r0 + 8, r0 + 8};
            int cc[4] = {c0, c0 + 1, c0, c0 + 1};
#pragma unroll
            for (int q = 0; q < 4; q++) {
                int m = rr[q], n = cc[q];
                float x = v[q];
                if (Cf) Cf[(size_t)m * N + n] = x;
                if (C2) {
                    bf16 h = __float2bfloat16(x);
                    size_t base = (size_t)m * 2 * C2K;
                    C2[base + n] = h;
                    C2[base + C2K + n] = __float2bfloat16(x - __bfloat162float(h));
                }
                if (Cscat) {
                    int t = m >> 4, bb_ = m & 15;
                    Cscat[((bb_ << 5) + t) * 1024 + n] = x;
                }
            }
        }
}

// ---------------- LSTM step (validated) ----------------
__global__ __launch_bounds__(256) void k_lstm_step(
    const float* __restrict__ Whh_f, const float* __restrict__ Whh_b, int s)
{
    __shared__ float sbuf[8192];
    int dir = blockIdx.x & 1;
    int h0 = (blockIdx.x >> 1) << 5;
    int t = dir ? (31 - s) : s;
    const float* __restrict__ Whh = dir ? Whh_b : Whh_f;
    int tid = threadIdx.x;
    {
        const float4* hp4 = (const float4*)(g_hT[s & 1] + dir * 8192);
        float4* sb4 = (float4*)sbuf;
#pragma unroll
        for (int i = 0; i < 8; i++) sb4[tid + i * 256] = hp4[tid + i * 256];
    }
    __syncthreads();
    int kq = tid >> 6;
    int sub = tid & 63;
    int gate = sub >> 4;
    int hg = sub & 15;
    int h = h0 + (hg << 1);
    const float* wr0 = Whh + (size_t)(gate * 512 + h) * 512 + (kq << 7);
    const float* wr1 = wr0 + 512;
    unsigned long long acc[2][8];
#pragma unroll
    for (int p = 0; p < 2; p++)
#pragma unroll
        for (int j = 0; j < 8; j++) acc[p][j] = 0ull;

    for (int k4 = 0; k4 < 128; k4 += 4) {
        float4 wa = *(const float4*)(wr0 + k4);
        float4 wb = *(const float4*)(wr1 + k4);
        float wav[4] = {wa.x, wa.y, wa.z, wa.w};
        float wbv[4] = {wb.x, wb.y, wb.z, wb.w};
#pragma unroll
        for (int j = 0; j < 4; j++) {
            int k = (kq << 7) + k4 + j;
            unsigned long long w2a = pk(wav[j], wav[j]);
            unsigned long long w2b = pk(wbv[j], wbv[j]);
            const ulonglong2* hb = (const ulonglong2*)&sbuf[k << 4];
            ulonglong2 q0 = hb[0], q1 = hb[1], q2 = hb[2], q3 = hb[3];
            fma2(acc[0][0], w2a, q0.x); fma2(acc[0][1], w2a, q0.y);
            fma2(acc[0][2], w2a, q1.x); fma2(acc[0][3], w2a, q1.y);
            fma2(acc[0][4], w2a, q2.x); fma2(acc[0][5], w2a, q2.y);
            fma2(acc[0][6], w2a, q3.x); fma2(acc[0][7], w2a, q3.y);
            fma2(acc[1][0], w2b, q0.x); fma2(acc[1][1], w2b, q0.y);
            fma2(acc[1][2], w2b, q1.x); fma2(acc[1][3], w2b, q1.y);
            fma2(acc[1][4], w2b, q2.x); fma2(acc[1][5], w2b, q2.y);
            fma2(acc[1][6], w2b, q3.x); fma2(acc[1][7], w2b, q3.y);
        }
    }
    __syncthreads();
#pragma unroll
    for (int p = 0; p < 2; p++)
#pragma unroll
        for (int j = 0; j < 8; j++) {
            float2 v = upk(acc[p][j]);
            int base = ((((kq << 2) + gate) * 16 + hg) * 2 + p) * 16 + (j << 1);
            sbuf[base] = v.x;
            sbuf[base + 1] = v.y;
        }
    __syncthreads();
    const float* gx = g_gx + ((size_t)dir * 512 + t * 16) * 2048;
    float* hNext = g_hT[(s + 1) & 1];
    for (int it = tid; it < 512; it += 256) {
        int hloc = it >> 4, b = it & 15;
        int hgl = hloc >> 1, p = hloc & 1;
        float v[4];
#pragma unroll
        for (int g2 = 0; g2 < 4; g2++) {
            int bi = ((g2 * 16 + hgl) * 2 + p) * 16 + b;
            v[g2] = sbuf[bi] + sbuf[bi + 2048] + sbuf[bi + 4096] + sbuf[bi + 6144]
                  + gx[(size_t)b * 2048 + g2 * 512 + h0 + hloc];
        }
        float i_ = 1.f / (1.f + expf(-v[0]));
        float f_ = 1.f / (1.f + expf(-v[1]));
        float gg = tanhf(v[2]);
        float o_ = 1.f / (1.f + expf(-v[3]));
        int hh = h0 + hloc;
        int ci = dir * 8192 + hh * 16 + b;
        float c = f_ * g_cT[ci] + i_ * gg;
        g_cT[ci] = c;
        float hn = o_ * tanhf(c);
        hNext[ci] = hn;
        g_hseq[(t * 16 + b) * 1024 + dir * 512 + hh] = hn;
    }
}

// ---------------- attention: scores with 4-t x reuse (128 CTAs) ----------------
__global__ __launch_bounds__(256) void k_att_scores(
    const float* __restrict__ w_att, const float* __restrict__ b_att)
{
    __shared__ float hm[4][512];
    __shared__ float wv[512];
    int b = blockIdx.x & 15, tg = blockIdx.x >> 4;   // tg 0..7
    int tid = threadIdx.x;
    wv[tid] = w_att[tid];
    wv[tid + 256] = w_att[tid + 256];
#pragma unroll
    for (int t4 = 0; t4 < 4; t4++) {
        int row = (tg * 4 + t4) * 16 + b;
        hm[t4][tid] = g_hemA[row * 512 + tid];
        hm[t4][tid + 256] = g_hemA[row * 512 + tid + 256];
    }
    __syncthreads();
    int lane = tid & 31, wrp = tid >> 5;
    float batt = b_att[0];
    const float* xb = g_xt + (size_t)b * 256 * 512;
    for (int hw = wrp; hw < 256; hw += 8) {
        const float* xr = xb + hw * 512;
        float s[4] = {0.f, 0.f, 0.f, 0.f};
        for (int e = lane; e < 512; e += 32) {
            float xv = xr[e], we = wv[e];
#pragma unroll
            for (int t4 = 0; t4 < 4; t4++) s[t4] += we * tanh_fast(xv + hm[t4][e]);
        }
#pragma unroll
        for (int o = 16; o; o >>= 1)
#pragma unroll
            for (int t4 = 0; t4 < 4; t4++) s[t4] += __shfl_xor_sync(0xffffffffu, s[t4], o);
        if (lane == 0)
#pragma unroll
            for (int t4 = 0; t4 < 4; t4++)
                g_sc[((tg * 4 + t4) * 16 + b) * 256 + hw] = s[t4] + batt;
    }
}

// ---------------- attention: softmax per (t,b) row ----------------
__global__ __launch_bounds__(256) void k_att_soft() {
    __shared__ float red[256];
    int r = blockIdx.x;
    int tid = threadIdx.x;
    float sv = g_sc[r * 256 + tid];
    red[tid] = sv;
    __syncthreads();
    for (int st = 128; st; st >>= 1) {
        if (tid < st) red[tid] = fmaxf(red[tid], red[tid + st]);
        __syncthreads();
    }
    float mx = red[0];
    __syncthreads();
    float e = expf(sv - mx);
    red[tid] = e;
    __syncthreads();
    for (int st = 128; st; st >>= 1) {
        if (tid < st) red[tid] += red[tid + st];
        __syncthreads();
    }
    g_alpha[r * 256 + tid] = e / red[0];
}

// ---------------- attention: weighted sum with 4-t x reuse (128 CTAs) --------
__global__ __launch_bounds__(256) void k_att_wsum(float* __restrict__ out) {
    __shared__ float al[4][256];
    int b = blockIdx.x & 15, tg = blockIdx.x >> 4;   // tg 0..7
    int tid = threadIdx.x;
#pragma unroll
    for (int t4 = 0; t4 < 4; t4++)
        al[t4][tid] = g_alpha[((tg * 4 + t4) * 16 + b) * 256 + tid];
    __syncthreads();
    const float* xb = g_xt + (size_t)b * 256 * 512;
    float a0[4] = {0.f, 0.f, 0.f, 0.f};
    float a1[4] = {0.f, 0.f, 0.f, 0.f};
    for (int hw = 0; hw < 256; hw++) {
        float x0 = xb[hw * 512 + tid];
        float x1 = xb[hw * 512 + tid + 256];
#pragma unroll
        for (int t4 = 0; t4 < 4; t4++) {
            float av = al[t4][hw];
            a0[t4] += av * x0;
            a1[t4] += av * x1;
        }
    }
#pragma unroll
    for (int t4 = 0; t4 < 4; t4++) {
        float* orow = out + (size_t)((b << 5) + tg * 4 + t4) * 1024 + 512;
        orow[tid] = a0[t4];
        orow[tid + 256] = a1[t4];
    }
}

// ---------------- launch ----------------
extern "C" void kernel_launch(void* const* d_in, const int* in_sizes, int n_in,
                              void* d_out, int out_size) {
    const float* hidden_en = (const float*)d_in[0];
    const float* conv_f = (const float*)d_in[1];
    const float* W_ih_f = (const float*)d_in[2];
    const float* W_hh_f = (const float*)d_in[3];
    const float* b_ih_f = (const float*)d_in[4];
    const float* b_hh_f = (const float*)d_in[5];
    const float* W_ih_b = (const float*)d_in[6];
    const float* W_hh_b = (const float*)d_in[7];
    const float* b_ih_b = (const float*)d_in[8];
    const float* b_hh_b = (const float*)d_in[9];
    const float* W_dec = (const float*)d_in[10];
    const float* b_dec = (const float*)d_in[11];
    const float* W_em = (const float*)d_in[12];
    const float* b_em = (const float*)d_in[13];
    const float* W_hem = (const float*)d_in[14];
    const float* b_hem = (const float*)d_in[15];
    const float* w_att = (const float*)d_in[16];
    const float* b_att = (const float*)d_in[17];
    float* out = (float*)d_out;

#define SYM(p, s) void* p; cudaGetSymbolAddress(&p, s)
    SYM(p_gx, g_gx); SYM(p_xt, g_xt); SYM(p_hseq, g_hseq); SYM(p_hem, g_hemA);
    SYM(p_col2, g_col2); SYM(p_wem2, g_wem2); SYM(p_en2, g_en2);
    SYM(p_wf2, g_wihf2); SYM(p_wb2, g_wihb2);
    SYM(p_wd2, g_wdec2); SYM(p_wh2, g_whem2);
    SYM(p_hs2, g_hseq2); SYM(p_hd2, g_hde2);

    // launches 1-3, then conv GEMM as launch #4 (ncu profiles launch #4)
    k_zero<<<64, 256>>>();
    k_im2col2<<<(4096 * 4608) / 256, 256>>>(conv_f);
    k_cvt2<<<(512 * 4608) / 256, 256>>>(W_em, (bf16*)p_wem2, 4608, 512 * 4608);
    // launch 4: conv GEMM -> g_xt (M=4096, N=512, K=4608)
    k_mma_gemm<<<dim3(4, 32), 256>>>((bf16*)p_col2, (bf16*)p_wem2, b_em, nullptr,
                                     (float*)p_xt, nullptr, 0, nullptr, 512, 4608);
    // remaining converts
    k_cvt2<<<(512 * 512) / 256, 256>>>(hidden_en, (bf16*)p_en2, 512, 512 * 512);
    k_cvt2<<<(2048 * 512) / 256, 256>>>(W_ih_f, (bf16*)p_wf2, 512, 2048 * 512);
    k_cvt2<<<(2048 * 512) / 256, 256>>>(W_ih_b, (bf16*)p_wb2, 512, 2048 * 512);
    k_cvt2<<<(512 * 1024) / 256, 256>>>(W_dec, (bf16*)p_wd2, 1024, 512 * 1024);
    k_cvt2<<<(512 * 512) / 256, 256>>>(W_hem, (bf16*)p_wh2, 512, 512 * 512);

    // input projections (M=512, N=2048, K=512)
    k_mma_gemm<<<dim3(16, 4), 256>>>((bf16*)p_en2, (bf16*)p_wf2, b_ih_f, b_hh_f,
                                     (float*)p_gx, nullptr, 0, nullptr, 2048, 512);
    k_mma_gemm<<<dim3(16, 4), 256>>>((bf16*)p_en2, (bf16*)p_wb2, b_ih_b, b_hh_b,
                                     (float*)p_gx + 512 * 2048, nullptr, 0, nullptr, 2048, 512);

    for (int s = 0; s < 32; s++) k_lstm_step<<<32, 256>>>(W_hh_f, W_hh_b, s);

    k_cvt2<<<(512 * 1024) / 256, 256>>>((float*)p_hseq, (bf16*)p_hs2, 1024, 512 * 1024);
    // dec (M=512, N=512, K=1024): scatter hidden_de into out + [hi|lo] hde
    k_mma_gemm<<<dim3(4, 4), 256>>>((bf16*)p_hs2, (bf16*)p_wd2, b_dec, nullptr,
                                    nullptr, (bf16*)p_hd2, 512, out, 512, 1024);
    // hem (M=512, N=512, K=512)
    k_mma_gemm<<<dim3(4, 4), 256>>>((bf16*)p_hd2, (bf16*)p_wh2, b_hem, nullptr,
                                    (float*)p_hem, nullptr, 0, nullptr, 512, 512);

    // attention
    k_att_scores<<<128, 256>>>(w_att, b_att);
    k_att_soft<<<512, 256>>>();
    k_att_wsum<<<128, 256>>>(out);
}

// round 13
// speedup vs baseline: 1.1069x; 1.0385x over previous
#include <cuda_runtime.h>
#include <cuda_bf16.h>
#include <math.h>
#include <stdint.h>

typedef __nv_bfloat16 bf16;

// ---------------- scratch ----------------
__device__ float g_hT[2][16384];
__device__ float g_cT[16384];
__device__ float g_hseq[512 * 1024];
__device__ float g_gx[2 * 512 * 2048];
__device__ float g_hemA[512 * 512];
__device__ float g_xt[4096 * 512];
__device__ float g_sc[512 * 256];
__device__ float g_alpha[512 * 256];
__device__ bf16 g_col2[4096u * 9216u];          // [hi(4608) | lo(4608)]
__device__ bf16 g_wem2[512 * 9216];
__device__ bf16 g_en2[512 * 1024];
__device__ bf16 g_wihf2[2048 * 1024], g_wihb2[2048 * 1024];
__device__ bf16 g_wdec2[512 * 2048];
__device__ bf16 g_whem2[512 * 1024];
__device__ bf16 g_hseq2[512 * 2048];
__device__ bf16 g_hde2[512 * 1024];

// ---------------- helpers ----------------
__device__ __forceinline__ void fma2(unsigned long long& d, unsigned long long a, unsigned long long b) {
    asm("fma.rn.f32x2 %0, %1, %2, %0;" : "+l"(d) : "l"(a), "l"(b));
}
__device__ __forceinline__ unsigned long long pk(float lo, float hi) {
    unsigned long long r;
    asm("mov.b64 %0, {%1, %2};" : "=l"(r) : "f"(lo), "f"(hi));
    return r;
}
__device__ __forceinline__ float2 upk(unsigned long long v) {
    float2 f;
    asm("mov.b64 {%0, %1}, %2;" : "=f"(f.x), "=f"(f.y) : "l"(v));
    return f;
}
__device__ __forceinline__ float tanh_fast(float x) {
    float y;
    asm("tanh.approx.f32 %0, %1;" : "=f"(y) : "f"(x));
    return y;
}
__device__ __forceinline__ uint32_t smem_u32(const void* p) {
    uint32_t a;
    asm("{ .reg .u64 t; cvta.to.shared.u64 t, %1; cvt.u32.u64 %0, t; }" : "=r"(a) : "l"(p));
    return a;
}
__device__ __forceinline__ void ldsm4(uint32_t& r0, uint32_t& r1, uint32_t& r2, uint32_t& r3,
                                      uint32_t addr) {
    asm volatile("ldmatrix.sync.aligned.m8n8.x4.shared.b16 {%0,%1,%2,%3}, [%4];"
                 : "=r"(r0), "=r"(r1), "=r"(r2), "=r"(r3) : "r"(addr));
}

// ---------------- init & converts ----------------
__global__ void k_zero() {
    int i = blockIdx.x * 256 + threadIdx.x;
    g_hT[0][i] = 0.f;
    g_cT[i] = 0.f;
}
__global__ void k_cvt2(const float* __restrict__ s, bf16* __restrict__ d, int K, int n) {
    int i = blockIdx.x * 256 + threadIdx.x;
    if (i >= n) return;
    int m = i / K, k = i % K;
    float v = s[i];
    bf16 h = __float2bfloat16(v);
    bf16 l = __float2bfloat16(v - __bfloat162float(h));
    size_t base = (size_t)m * 2 * K;
    d[base + k] = h;
    d[base + K + k] = l;
}
__global__ void k_im2col2(const float* __restrict__ cf) {
    int idx = blockIdx.x * 256 + threadIdx.x;   // < 4096*4608
    int k = idx % 4608, m = idx / 4608;
    int kw = k % 3, kh = (k / 3) % 3, c = k / 9;
    int w = m & 31, h = (m >> 5) & 7, b = m >> 8;
    int ih = h + kh - 1, iw = w + kw - 1;
    float v = 0.f;
    if (ih >= 0 && ih < 8 && iw >= 0 && iw < 32) v = cf[((b * 512 + c) * 8 + ih) * 32 + iw];
    bf16 hv = __float2bfloat16(v);
    size_t base = (size_t)m * 9216;
    g_col2[base + k] = hv;
    g_col2[base + 4608 + k] = __float2bfloat16(v - __bfloat162float(hv));
}

// ---------------- HMMA bf16 NT GEMM: ldmatrix + 3-stage cp.async ----------------
#define PAD 40
#define TSZB 10240u   // 128 rows * 40 elem * 2B per stage
__device__ __forceinline__ void ld_chunk(uint32_t ds, const bf16* __restrict__ src,
                                         int row0, int rs, int koff, int tid) {
#pragma unroll
    for (int j = 0; j < 2; j++) {
        int ch = tid + (j << 8);
        int row = ch >> 2, c = ch & 3;
        const void* g = src + (size_t)(row0 + row) * rs + koff + (c << 3);
        uint32_t d = ds + (row * PAD + (c << 3)) * 2;
        asm volatile("cp.async.ca.shared.global [%0], [%1], 16;" :: "r"(d), "l"(g) : "memory");
    }
}

__global__ __launch_bounds__(256) void k_mma_gemm(
    const bf16* __restrict__ A2, const bf16* __restrict__ B2,
    const float* __restrict__ bias, const float* __restrict__ bias2,
    float* __restrict__ Cf, bf16* __restrict__ C2, int C2K,
    float* __restrict__ Cscat, int N, int K)
{
    extern __shared__ __align__(16) char dsm[];
    uint32_t asb = smem_u32(dsm);            // A stages at asb + st*TSZB
    uint32_t bsb = asb + 3 * TSZB;           // B stages
    int tid = threadIdx.x, lane = tid & 31, wid = tid >> 5;
    int g = lane >> 2, t2 = (lane & 3) << 1;
    int bm = blockIdx.y << 7, bn = blockIdx.x << 7;
    int wm = (wid >> 1) << 5, wn = (wid & 1) << 6;
    int rs = K << 1;
    int KC = K >> 5, S = KC * 3;

    // per-lane ldmatrix byte offsets within a stage
    int lr8 = lane & 7, half = (lane >> 3) & 1, quad = lane >> 4;
    uint32_t aoffB[2], boffB[4];
#pragma unroll
    for (int mt = 0; mt < 2; mt++)
        aoffB[mt] = ((wm + (mt << 4) + lr8 + (half << 3)) * PAD + (quad << 3)) * 2;
#pragma unroll
    for (int np = 0; np < 4; np++)
        boffB[np] = ((wn + (np << 4) + (quad << 3) + lr8) * PAD + (half << 3)) * 2;

    float acc[2][8][4];
#pragma unroll
    for (int mt = 0; mt < 2; mt++)
#pragma unroll
        for (int nt = 0; nt < 8; nt++)
#pragma unroll
            for (int q = 0; q < 4; q++) acc[mt][nt][q] = 0.f;

    // prologue: stages 0 and 1
#pragma unroll
    for (int st = 0; st < 2; st++) {
        int p = st / KC, cc = st - p * KC;
        int ao = ((p == 2) ? K : 0) + (cc << 5);
        int bo = ((p == 1) ? K : 0) + (cc << 5);
        ld_chunk(asb + st * TSZB, A2, bm, rs, ao, tid);
        ld_chunk(bsb + st * TSZB, B2, bn, rs, bo, tid);
        asm volatile("cp.async.commit_group;" ::: "memory");
    }

    for (int s = 0; s < S; s++) {
        if (s == S - 1) asm volatile("cp.async.wait_group 0;" ::: "memory");
        else            asm volatile("cp.async.wait_group 1;" ::: "memory");
        __syncthreads();
        if (s + 2 < S) {
            int st = s + 2, bufn = st % 3;
            int p = st / KC, cc = st - p * KC;
            int ao = ((p == 2) ? K : 0) + (cc << 5);
            int bo = ((p == 1) ? K : 0) + (cc << 5);
            ld_chunk(asb + bufn * TSZB, A2, bm, rs, ao, tid);
            ld_chunk(bsb + bufn * TSZB, B2, bn, rs, bo, tid);
            asm volatile("cp.async.commit_group;" ::: "memory");
        }
        uint32_t ab = asb + (uint32_t)(s % 3) * TSZB;
        uint32_t bb = bsb + (uint32_t)(s % 3) * TSZB;
#pragma unroll
        for (int kk = 0; kk < 2; kk++) {
            uint32_t kby = (uint32_t)(kk << 5);   // 16 elems * 2B
            uint32_t a[2][4], b[8][2];
#pragma unroll
            for (int mt = 0; mt < 2; mt++)
                ldsm4(a[mt][0], a[mt][1], a[mt][2], a[mt][3], ab + aoffB[mt] + kby);
#pragma unroll
            for (int np = 0; np < 4; np++)
                ldsm4(b[2 * np][0], b[2 * np][1], b[2 * np + 1][0], b[2 * np + 1][1],
                      bb + boffB[np] + kby);
#pragma unroll
            for (int mt = 0; mt < 2; mt++)
#pragma unroll
                for (int nt = 0; nt < 8; nt++)
                    asm volatile(
                        "mma.sync.aligned.m16n8k16.row.col.f32.bf16.bf16.f32 "
                        "{%0,%1,%2,%3},{%4,%5,%6,%7},{%8,%9},{%0,%1,%2,%3};"
                        : "+f"(acc[mt][nt][0]), "+f"(acc[mt][nt][1]),
                          "+f"(acc[mt][nt][2]), "+f"(acc[mt][nt][3])
                        : "r"(a[mt][0]), "r"(a[mt][1]), "r"(a[mt][2]), "r"(a[mt][3]),
                          "r"(b[nt][0]), "r"(b[nt][1]));
        }
    }
#pragma unroll
    for (int mt = 0; mt < 2; mt++)
#pragma unroll
        for (int nt = 0; nt < 8; nt++) {
            int r0 = bm + wm + (mt << 4) + g;
            int c0 = bn + wn + (nt << 3) + t2;
            float bv0 = bias[c0] + (bias2 ? bias2[c0] : 0.f);
            float bv1 = bias[c0 + 1] + (bias2 ? bias2[c0 + 1] : 0.f);
            float v[4] = {acc[mt][nt][0] + bv0, acc[mt][nt][1] + bv1,
                          acc[mt][nt][2] + bv0, acc[mt][nt][3] + bv1};
            int rr[4] = {r0, r0, r0 + 8, r0 + 8};
            int cc[4] = {c0, c0 + 1, c0, c0 + 1};
#pragma unroll
            for (int q = 0; q < 4; q++) {
                int m = rr[q], n = cc[q];
                float x = v[q];
                if (Cf) Cf[(size_t)m * N + n] = x;
                if (C2) {
                    bf16 h = __float2bfloat16(x);
                    size_t base = (size_t)m * 2 * C2K;
                    C2[base + n] = h;
                    C2[base + C2K + n] = __float2bfloat16(x - __bfloat162float(h));
                }
                if (Cscat) {
                    int t = m >> 4, bb_ = m & 15;
                    Cscat[((bb_ << 5) + t) * 1024 + n] = x;
                }
            }
        }
}

// ---------------- LSTM step (validated) ----------------
__global__ __launch_bounds__(256) void k_lstm_step(
    const float* __restrict__ Whh_f, const float* __restrict__ Whh_b, int s)
{
    __shared__ float sbuf[8192];
    int dir = blockIdx.x & 1;
    int h0 = (blockIdx.x >> 1) << 5;
    int t = dir ? (31 - s) : s;
    const float* __restrict__ Whh = dir ? Whh_b : Whh_f;
    int tid = threadIdx.x;
    {
        const float4* hp4 = (const float4*)(g_hT[s & 1] + dir * 8192);
        float4* sb4 = (float4*)sbuf;
#pragma unroll
        for (int i = 0; i < 8; i++) sb4[tid + i * 256] = hp4[tid + i * 256];
    }
    __syncthreads();
    int kq = tid >> 6;
    int sub = tid & 63;
    int gate = sub >> 4;
    int hg = sub & 15;
    int h = h0 + (hg << 1);
    const float* wr0 = Whh + (size_t)(gate * 512 + h) * 512 + (kq << 7);
    const float* wr1 = wr0 + 512;
    unsigned long long acc[2][8];
#pragma unroll
    for (int p = 0; p < 2; p++)
#pragma unroll
        for (int j = 0; j < 8; j++) acc[p][j] = 0ull;

    for (int k4 = 0; k4 < 128; k4 += 4) {
        float4 wa = *(const float4*)(wr0 + k4);
        float4 wb = *(const float4*)(wr1 + k4);
        float wav[4] = {wa.x, wa.y, wa.z, wa.w};
        float wbv[4] = {wb.x, wb.y, wb.z, wb.w};
#pragma unroll
        for (int j = 0; j < 4; j++) {
            int k = (kq << 7) + k4 + j;
            unsigned long long w2a = pk(wav[j], wav[j]);
            unsigned long long w2b = pk(wbv[j], wbv[j]);
            const ulonglong2* hb = (const ulonglong2*)&sbuf[k << 4];
            ulonglong2 q0 = hb[0], q1 = hb[1], q2 = hb[2], q3 = hb[3];
            fma2(acc[0][0], w2a, q0.x); fma2(acc[0][1], w2a, q0.y);
            fma2(acc[0][2], w2a, q1.x); fma2(acc[0][3], w2a, q1.y);
            fma2(acc[0][4], w2a, q2.x); fma2(acc[0][5], w2a, q2.y);
            fma2(acc[0][6], w2a, q3.x); fma2(acc[0][7], w2a, q3.y);
            fma2(acc[1][0], w2b, q0.x); fma2(acc[1][1], w2b, q0.y);
            fma2(acc[1][2], w2b, q1.x); fma2(acc[1][3], w2b, q1.y);
            fma2(acc[1][4], w2b, q2.x); fma2(acc[1][5], w2b, q2.y);
            fma2(acc[1][6], w2b, q3.x); fma2(acc[1][7], w2b, q3.y);
        }
    }
    __syncthreads();
#pragma unroll
    for (int p = 0; p < 2; p++)
#pragma unroll
        for (int j = 0; j < 8; j++) {
            float2 v = upk(acc[p][j]);
            int base = ((((kq << 2) + gate) * 16 + hg) * 2 + p) * 16 + (j << 1);
            sbuf[base] = v.x;
            sbuf[base + 1] = v.y;
        }
    __syncthreads();
    const float* gx = g_gx + ((size_t)dir * 512 + t * 16) * 2048;
    float* hNext = g_hT[(s + 1) & 1];
    for (int it = tid; it < 512; it += 256) {
        int hloc = it >> 4, b = it & 15;
        int hgl = hloc >> 1, p = hloc & 1;
        float v[4];
#pragma unroll
        for (int g2 = 0; g2 < 4; g2++) {
            int bi = ((g2 * 16 + hgl) * 2 + p) * 16 + b;
            v[g2] = sbuf[bi] + sbuf[bi + 2048] + sbuf[bi + 4096] + sbuf[bi + 6144]
                  + gx[(size_t)b * 2048 + g2 * 512 + h0 + hloc];
        }
        float i_ = 1.f / (1.f + expf(-v[0]));
        float f_ = 1.f / (1.f + expf(-v[1]));
        float gg = tanhf(v[2]);
        float o_ = 1.f / (1.f + expf(-v[3]));
        int hh = h0 + hloc;
        int ci = dir * 8192 + hh * 16 + b;
        float c = f_ * g_cT[ci] + i_ * gg;
        g_cT[ci] = c;
        float hn = o_ * tanhf(c);
        hNext[ci] = hn;
        g_hseq[(t * 16 + b) * 1024 + dir * 512 + hh] = hn;
    }
}

// ---------------- attention: scores with 4-t x reuse (128 CTAs) ----------------
__global__ __launch_bounds__(256) void k_att_scores(
    const float* __restrict__ w_att, const float* __restrict__ b_att)
{
    __shared__ float hm[4][512];
    __shared__ float wv[512];
    int b = blockIdx.x & 15, tg = blockIdx.x >> 4;   // tg 0..7
    int tid = threadIdx.x;
    wv[tid] = w_att[tid];
    wv[tid + 256] = w_att[tid + 256];
#pragma unroll
    for (int t4 = 0; t4 < 4; t4++) {
        int row = (tg * 4 + t4) * 16 + b;
        hm[t4][tid] = g_hemA[row * 512 + tid];
        hm[t4][tid + 256] = g_hemA[row * 512 + tid + 256];
    }
    __syncthreads();
    int lane = tid & 31, wrp = tid >> 5;
    float batt = b_att[0];
    const float* xb = g_xt + (size_t)b * 256 * 512;
    for (int hw = wrp; hw < 256; hw += 8) {
        const float* xr = xb + hw * 512;
        float s[4] = {0.f, 0.f, 0.f, 0.f};
        for (int e = lane; e < 512; e += 32) {
            float xv = xr[e], we = wv[e];
#pragma unroll
            for (int t4 = 0; t4 < 4; t4++) s[t4] += we * tanh_fast(xv + hm[t4][e]);
        }
#pragma unroll
        for (int o = 16; o; o >>= 1)
#pragma unroll
            for (int t4 = 0; t4 < 4; t4++) s[t4] += __shfl_xor_sync(0xffffffffu, s[t4], o);
        if (lane == 0)
#pragma unroll
            for (int t4 = 0; t4 < 4; t4++)
                g_sc[((tg * 4 + t4) * 16 + b) * 256 + hw] = s[t4] + batt;
    }
}

// ---------------- attention: softmax per (t,b) row ----------------
__global__ __launch_bounds__(256) void k_att_soft() {
    __shared__ float red[256];
    int r = blockIdx.x;
    int tid = threadIdx.x;
    float sv = g_sc[r * 256 + tid];
    red[tid] = sv;
    __syncthreads();
    for (int st = 128; st; st >>= 1) {
        if (tid < st) red[tid] = fmaxf(red[tid], red[tid + st]);
        __syncthreads();
    }
    float mx = red[0];
    __syncthreads();
    float e = expf(sv - mx);
    red[tid] = e;
    __syncthreads();
    for (int st = 128; st; st >>= 1) {
        if (tid < st) red[tid] += red[tid + st];
        __syncthreads();
    }
    g_alpha[r * 256 + tid] = e / red[0];
}

// ---------------- attention: weighted sum with 4-t x reuse (128 CTAs) --------
__global__ __launch_bounds__(256) void k_att_wsum(float* __restrict__ out) {
    __shared__ float al[4][256];
    int b = blockIdx.x & 15, tg = blockIdx.x >> 4;   // tg 0..7
    int tid = threadIdx.x;
#pragma unroll
    for (int t4 = 0; t4 < 4; t4++)
        al[t4][tid] = g_alpha[((tg * 4 + t4) * 16 + b) * 256 + tid];
    __syncthreads();
    const float* xb = g_xt + (size_t)b * 256 * 512;
    float a0[4] = {0.f, 0.f, 0.f, 0.f};
    float a1[4] = {0.f, 0.f, 0.f, 0.f};
    for (int hw = 0; hw < 256; hw++) {
        float x0 = xb[hw * 512 + tid];
        float x1 = xb[hw * 512 + tid + 256];
#pragma unroll
        for (int t4 = 0; t4 < 4; t4++) {
            float av = al[t4][hw];
            a0[t4] += av * x0;
            a1[t4] += av * x1;
        }
    }
#pragma unroll
    for (int t4 = 0; t4 < 4; t4++) {
        float* orow = out + (size_t)((b << 5) + tg * 4 + t4) * 1024 + 512;
        orow[tid] = a0[t4];
        orow[tid + 256] = a1[t4];
    }
}

// ---------------- launch ----------------
extern "C" void kernel_launch(void* const* d_in, const int* in_sizes, int n_in,
                              void* d_out, int out_size) {
    const float* hidden_en = (const float*)d_in[0];
    const float* conv_f = (const float*)d_in[1];
    const float* W_ih_f = (const float*)d_in[2];
    const float* W_hh_f = (const float*)d_in[3];
    const float* b_ih_f = (const float*)d_in[4];
    const float* b_hh_f = (const float*)d_in[5];
    const float* W_ih_b = (const float*)d_in[6];
    const float* W_hh_b = (const float*)d_in[7];
    const float* b_ih_b = (const float*)d_in[8];
    const float* b_hh_b = (const float*)d_in[9];
    const float* W_dec = (const float*)d_in[10];
    const float* b_dec = (const float*)d_in[11];
    const float* W_em = (const float*)d_in[12];
    const float* b_em = (const float*)d_in[13];
    const float* W_hem = (const float*)d_in[14];
    const float* b_hem = (const float*)d_in[15];
    const float* w_att = (const float*)d_in[16];
    const float* b_att = (const float*)d_in[17];
    float* out = (float*)d_out;

#define SYM(p, s) void* p; cudaGetSymbolAddress(&p, s)
    SYM(p_gx, g_gx); SYM(p_xt, g_xt); SYM(p_hseq, g_hseq); SYM(p_hem, g_hemA);
    SYM(p_col2, g_col2); SYM(p_wem2, g_wem2); SYM(p_en2, g_en2);
    SYM(p_wf2, g_wihf2); SYM(p_wb2, g_wihb2);
    SYM(p_wd2, g_wdec2); SYM(p_wh2, g_whem2);
    SYM(p_hs2, g_hseq2); SYM(p_hd2, g_hde2);

    const int SMB = 6 * 10240;   // 3-stage A+B
    cudaFuncSetAttribute(k_mma_gemm, cudaFuncAttributeMaxDynamicSharedMemorySize, SMB);

    // launches 1-3, then conv GEMM as launch #4 (ncu profiles launch #4)
    k_zero<<<64, 256>>>();
    k_im2col2<<<(4096 * 4608) / 256, 256>>>(conv_f);
    k_cvt2<<<(512 * 4608) / 256, 256>>>(W_em, (bf16*)p_wem2, 4608, 512 * 4608);
    // launch 4: conv GEMM -> g_xt (M=4096, N=512, K=4608)
    k_mma_gemm<<<dim3(4, 32), 256, SMB>>>((bf16*)p_col2, (bf16*)p_wem2, b_em, nullptr,
                                          (float*)p_xt, nullptr, 0, nullptr, 512, 4608);
    // remaining converts
    k_cvt2<<<(512 * 512) / 256, 256>>>(hidden_en, (bf16*)p_en2, 512, 512 * 512);
    k_cvt2<<<(2048 * 512) / 256, 256>>>(W_ih_f, (bf16*)p_wf2, 512, 2048 * 512);
    k_cvt2<<<(2048 * 512) / 256, 256>>>(W_ih_b, (bf16*)p_wb2, 512, 2048 * 512);
    k_cvt2<<<(512 * 1024) / 256, 256>>>(W_dec, (bf16*)p_wd2, 1024, 512 * 1024);
    k_cvt2<<<(512 * 512) / 256, 256>>>(W_hem, (bf16*)p_wh2, 512, 512 * 512);

    // input projections (M=512, N=2048, K=512)
    k_mma_gemm<<<dim3(16, 4), 256, SMB>>>((bf16*)p_en2, (bf16*)p_wf2, b_ih_f, b_hh_f,
                                          (float*)p_gx, nullptr, 0, nullptr, 2048, 512);
    k_mma_gemm<<<dim3(16, 4), 256, SMB>>>((bf16*)p_en2, (bf16*)p_wb2, b_ih_b, b_hh_b,
                                          (float*)p_gx + 512 * 2048, nullptr, 0, nullptr, 2048, 512);

    for (int s = 0; s < 32; s++) k_lstm_step<<<32, 256>>>(W_hh_f, W_hh_b, s);

    k_cvt2<<<(512 * 1024) / 256, 256>>>((float*)p_hseq, (bf16*)p_hs2, 1024, 512 * 1024);
    // dec (M=512, N=512, K=1024): scatter hidden_de into out + [hi|lo] hde
    k_mma_gemm<<<dim3(4, 4), 256, SMB>>>((bf16*)p_hs2, (bf16*)p_wd2, b_dec, nullptr,
                                         nullptr, (bf16*)p_hd2, 512, out, 512, 1024);
    // hem (M=512, N=512, K=512)
    k_mma_gemm<<<dim3(4, 4), 256, SMB>>>((bf16*)p_hd2, (bf16*)p_wh2, b_hem, nullptr,
                                         (float*)p_hem, nullptr, 0, nullptr, 512, 512);

    // attention
    k_att_scores<<<128, 256>>>(w_att, b_att);
    k_att_soft<<<512, 256>>>();
    k_att_wsum<<<128, 256>>>(out);
}

// round 16
// speedup vs baseline: 1.5422x; 1.3933x over previous
#include <cuda_runtime.h>
#include <cuda_bf16.h>
#include <math.h>
#include <stdint.h>

typedef __nv_bfloat16 bf16;

// ---------------- scratch ----------------
__device__ float g_hT[2][16384];
__device__ float g_cT[16384];
__device__ float g_hseq[512 * 1024];
__device__ float g_gx[2 * 512 * 2048];
__device__ float g_hemA[512 * 512];
__device__ float g_xt[4096 * 512];
__device__ float g_sc[512 * 256];
__device__ float g_alpha[512 * 256];
__device__ bf16 g_col2[4096u * 9216u];          // [hi(4608) | lo(4608)]
__device__ bf16 g_wem2[512 * 9216];
__device__ bf16 g_en2[512 * 1024];
__device__ bf16 g_wihf2[2048 * 1024], g_wihb2[2048 * 1024];
__device__ bf16 g_wdec2[512 * 2048];
__device__ bf16 g_whem2[512 * 1024];
__device__ bf16 g_hseq2[512 * 2048];
__device__ bf16 g_hde2[512 * 1024];

// ---------------- helpers ----------------
__device__ __forceinline__ void fma2(unsigned long long& d, unsigned long long a, unsigned long long b) {
    asm("fma.rn.f32x2 %0, %1, %2, %0;" : "+l"(d) : "l"(a), "l"(b));
}
__device__ __forceinline__ float2 upk(unsigned long long v) {
    float2 f;
    asm("mov.b64 {%0, %1}, %2;" : "=f"(f.x), "=f"(f.y) : "l"(v));
    return f;
}
__device__ __forceinline__ float tanh_fast(float x) {
    float y;
    asm("tanh.approx.f32 %0, %1;" : "=f"(y) : "f"(x));
    return y;
}
__device__ __forceinline__ uint32_t smem_u32(const void* p) {
    uint32_t a;
    asm("{ .reg .u64 t; cvta.to.shared.u64 t, %1; cvt.u32.u64 %0, t; }" : "=r"(a) : "l"(p));
    return a;
}
__device__ __forceinline__ void ldsm4(uint32_t& r0, uint32_t& r1, uint32_t& r2, uint32_t& r3,
                                      uint32_t addr) {
    asm volatile("ldmatrix.sync.aligned.m8n8.x4.shared.b16 {%0,%1,%2,%3}, [%4];"
                 : "=r"(r0), "=r"(r1), "=r"(r2), "=r"(r3) : "r"(addr));
}

// ---------------- init & converts ----------------
__global__ void k_zero() {
    int i = blockIdx.x * 256 + threadIdx.x;
    g_hT[0][i] = 0.f;
    g_cT[i] = 0.f;
}
__global__ void k_cvt2(const float* __restrict__ s, bf16* __restrict__ d, int K, int n) {
    int i = blockIdx.x * 256 + threadIdx.x;
    if (i >= n) return;
    int m = i / K, k = i % K;
    float v = s[i];
    bf16 h = __float2bfloat16(v);
    bf16 l = __float2bfloat16(v - __bfloat162float(h));
    size_t base = (size_t)m * 2 * K;
    d[base + k] = h;
    d[base + K + k] = l;
}
__global__ void k_im2col2(const float* __restrict__ cf) {
    int idx = blockIdx.x * 256 + threadIdx.x;   // < 4096*4608
    int k = idx % 4608, m = idx / 4608;
    int kw = k % 3, kh = (k / 3) % 3, c = k / 9;
    int w = m & 31, h = (m >> 5) & 7, b = m >> 8;
    int ih = h + kh - 1, iw = w + kw - 1;
    float v = 0.f;
    if (ih >= 0 && ih < 8 && iw >= 0 && iw < 32) v = cf[((b * 512 + c) * 8 + ih) * 32 + iw];
    bf16 hv = __float2bfloat16(v);
    size_t base = (size_t)m * 9216;
    g_col2[base + k] = hv;
    g_col2[base + 4608 + k] = __float2bfloat16(v - __bfloat162float(hv));
}

// ---------------- HMMA bf16 NT GEMM: ldmatrix + 3-stage cp.async (R13 core) ----
#define PAD 40
#define TSZB 10240u   // 128 rows * 40 elem * 2B per stage
__device__ __forceinline__ void ld_chunk(uint32_t ds, const bf16* __restrict__ src,
                                         int row0, int rs, int koff, int tid) {
#pragma unroll
    for (int j = 0; j < 2; j++) {
        int ch = tid + (j << 8);
        int row = ch >> 2, c = ch & 3;
        const void* g = src + (size_t)(row0 + row) * rs + koff + (c << 3);
        uint32_t d = ds + (row * PAD + (c << 3)) * 2;
        asm volatile("cp.async.ca.shared.global [%0], [%1], 16;" :: "r"(d), "l"(g) : "memory");
    }
}

__global__ __launch_bounds__(256) void k_mma_gemm(
    const bf16* __restrict__ A2, const bf16* __restrict__ B2,
    const float* __restrict__ bias, const float* __restrict__ bias2,
    float* __restrict__ Cf, bf16* __restrict__ C2, int C2K,
    float* __restrict__ Cscat, int N, int K)
{
    extern __shared__ __align__(16) char dsm[];
    uint32_t asb = smem_u32(dsm);            // A stages at asb + st*TSZB
    uint32_t bsb = asb + 3 * TSZB;           // B stages
    int tid = threadIdx.x, lane = tid & 31, wid = tid >> 5;
    int g = lane >> 2, t2 = (lane & 3) << 1;
    int bm = blockIdx.y << 7, bn = blockIdx.x << 7;
    int wm = (wid >> 1) << 5, wn = (wid & 1) << 6;
    int rs = K << 1;
    int KC = K >> 5, S = KC * 3;

    int lr8 = lane & 7, half = (lane >> 3) & 1, quad = lane >> 4;
    uint32_t aoffB[2], boffB[4];
#pragma unroll
    for (int mt = 0; mt < 2; mt++)
        aoffB[mt] = ((wm + (mt << 4) + lr8 + (half << 3)) * PAD + (quad << 3)) * 2;
#pragma unroll
    for (int np = 0; np < 4; np++)
        boffB[np] = ((wn + (np << 4) + (quad << 3) + lr8) * PAD + (half << 3)) * 2;

    float acc[2][8][4];
#pragma unroll
    for (int mt = 0; mt < 2; mt++)
#pragma unroll
        for (int nt = 0; nt < 8; nt++)
#pragma unroll
            for (int q = 0; q < 4; q++) acc[mt][nt][q] = 0.f;

    // prologue: stages 0 and 1
#pragma unroll
    for (int st = 0; st < 2; st++) {
        int p = st / KC, cc = st - p * KC;
        int ao = ((p == 2) ? K : 0) + (cc << 5);
        int bo = ((p == 1) ? K : 0) + (cc << 5);
        ld_chunk(asb + st * TSZB, A2, bm, rs, ao, tid);
        ld_chunk(bsb + st * TSZB, B2, bn, rs, bo, tid);
        asm volatile("cp.async.commit_group;" ::: "memory");
    }

    for (int s = 0; s < S; s++) {
        if (s == S - 1) asm volatile("cp.async.wait_group 0;" ::: "memory");
        else            asm volatile("cp.async.wait_group 1;" ::: "memory");
        __syncthreads();
        if (s + 2 < S) {
            int st = s + 2, bufn = st % 3;
            int p = st / KC, cc = st - p * KC;
            int ao = ((p == 2) ? K : 0) + (cc << 5);
            int bo = ((p == 1) ? K : 0) + (cc << 5);
            ld_chunk(asb + bufn * TSZB, A2, bm, rs, ao, tid);
            ld_chunk(bsb + bufn * TSZB, B2, bn, rs, bo, tid);
            asm volatile("cp.async.commit_group;" ::: "memory");
        }
        uint32_t ab = asb + (uint32_t)(s % 3) * TSZB;
        uint32_t bb = bsb + (uint32_t)(s % 3) * TSZB;
#pragma unroll
        for (int kk = 0; kk < 2; kk++) {
            uint32_t kby = (uint32_t)(kk << 5);   // 16 elems * 2B
            uint32_t a[2][4], b[8][2];
#pragma unroll
            for (int mt = 0; mt < 2; mt++)
                ldsm4(a[mt][0], a[mt][1], a[mt][2], a[mt][3], ab + aoffB[mt] + kby);
#pragma unroll
            for (int np = 0; np < 4; np++)
                ldsm4(b[2 * np][0], b[2 * np][1], b[2 * np + 1][0], b[2 * np + 1][1],
                      bb + boffB[np] + kby);
#pragma unroll
            for (int mt = 0; mt < 2; mt++)
#pragma unroll
                for (int nt = 0; nt < 8; nt++)
                    asm volatile(
                        "mma.sync.aligned.m16n8k16.row.col.f32.bf16.bf16.f32 "
                        "{%0,%1,%2,%3},{%4,%5,%6,%7},{%8,%9},{%0,%1,%2,%3};"
                        : "+f"(acc[mt][nt][0]), "+f"(acc[mt][nt][1]),
                          "+f"(acc[mt][nt][2]), "+f"(acc[mt][nt][3])
                        : "r"(a[mt][0]), "r"(a[mt][1]), "r"(a[mt][2]), "r"(a[mt][3]),
                          "r"(b[nt][0]), "r"(b[nt][1]));
        }
    }
#pragma unroll
    for (int mt = 0; mt < 2; mt++)
#pragma unroll
        for (int nt = 0; nt < 8; nt++) {
            int r0 = bm + wm + (mt << 4) + g;
            int c0 = bn + wn + (nt << 3) + t2;
            float bv0 = bias[c0] + (bias2 ? bias2[c0] : 0.f);
            float bv1 = bias[c0 + 1] + (bias2 ? bias2[c0 + 1] : 0.f);
            float v[4] = {acc[mt][nt][0] + bv0, acc[mt][nt][1] + bv1,
                          acc[mt][nt][2] + bv0, acc[mt][nt][3] + bv1};
            int rr[4] = {r0, r0, r0 + 8, r0 + 8};
            int cc[4] = {c0, c0 + 1, c0, c0 + 1};
#pragma unroll
            for (int q = 0; q < 4; q++) {
                int m = rr[q], n = cc[q];
                float x = v[q];
                if (Cf) Cf[(size_t)m * N + n] = x;
                if (C2) {
                    bf16 h = __float2bfloat16(x);
                    size_t base = (size_t)m * 2 * C2K;
                    C2[base + n] = h;
                    C2[base + C2K + n] = __float2bfloat16(x - __bfloat162float(h));
                }
                if (Cscat) {
                    int t = m >> 4, bb_ = m & 15;
                    Cscat[((bb_ << 5) + t) * 1024 + n] = x;
                }
            }
        }
}

// ---------------- LSTM step, 128 CTAs (h-tile 8, 16-way k-split) ----------------
__global__ __launch_bounds__(256) void k_lstm_step(
    const float* __restrict__ Whh_f, const float* __restrict__ Whh_b, int s)
{
    __shared__ float sbuf[8192];
    int dir = blockIdx.x & 1;
    int h0 = (blockIdx.x >> 1) << 3;              // 64 tiles of 8 h
    int t = dir ? (31 - s) : s;
    const float* __restrict__ Whh = dir ? Whh_b : Whh_f;
    int tid = threadIdx.x;
    {
        const float4* hp4 = (const float4*)(g_hT[s & 1] + dir * 8192);
        float4* sb4 = (float4*)sbuf;
#pragma unroll
        for (int i = 0; i < 8; i++) sb4[tid + i * 256] = hp4[tid + i * 256];
    }
    __syncthreads();
    int kq = tid >> 4;                 // 16 k-splits of 32
    int gate = (tid >> 2) & 3;
    int hp = tid & 3;                  // 2 h each
    int h = h0 + (hp << 1);
    const float* wr0 = Whh + (size_t)(gate * 512 + h) * 512 + (kq << 5);
    const float* wr1 = wr0 + 512;
    unsigned long long acc[2][8];
#pragma unroll
    for (int p = 0; p < 2; p++)
#pragma unroll
        for (int j = 0; j < 8; j++) acc[p][j] = 0ull;

    for (int k4 = 0; k4 < 32; k4 += 4) {
        float4 wa = *(const float4*)(wr0 + k4);
        float4 wb = *(const float4*)(wr1 + k4);
        float wav[4] = {wa.x, wa.y, wa.z, wa.w};
        float wbv[4] = {wb.x, wb.y, wb.z, wb.w};
#pragma unroll
        for (int j = 0; j < 4; j++) {
            int k = (kq << 5) + k4 + j;
            unsigned long long w2a, w2b;
            asm("mov.b64 %0, {%1, %1};" : "=l"(w2a) : "f"(wav[j]));
            asm("mov.b64 %0, {%1, %1};" : "=l"(w2b) : "f"(wbv[j]));
            const ulonglong2* hb = (const ulonglong2*)&sbuf[k << 4];
            ulonglong2 q0 = hb[0], q1 = hb[1], q2 = hb[2], q3 = hb[3];
            fma2(acc[0][0], w2a, q0.x); fma2(acc[0][1], w2a, q0.y);
            fma2(acc[0][2], w2a, q1.x); fma2(acc[0][3], w2a, q1.y);
            fma2(acc[0][4], w2a, q2.x); fma2(acc[0][5], w2a, q2.y);
            fma2(acc[0][6], w2a, q3.x); fma2(acc[0][7], w2a, q3.y);
            fma2(acc[1][0], w2b, q0.x); fma2(acc[1][1], w2b, q0.y);
            fma2(acc[1][2], w2b, q1.x); fma2(acc[1][3], w2b, q1.y);
            fma2(acc[1][4], w2b, q2.x); fma2(acc[1][5], w2b, q2.y);
            fma2(acc[1][6], w2b, q3.x); fma2(acc[1][7], w2b, q3.y);
        }
    }
    __syncthreads();   // done reading h; reuse sbuf for partials
#pragma unroll
    for (int p = 0; p < 2; p++)
#pragma unroll
        for (int j = 0; j < 8; j++) {
            float2 v = upk(acc[p][j]);
            int base = (kq << 9) + ((gate * 8 + (hp << 1) + p) << 4) + (j << 1);
            sbuf[base] = v.x;
            sbuf[base + 1] = v.y;
        }
    __syncthreads();
    if (tid < 128) {
        int hloc = tid >> 4, b = tid & 15;
        const float* gx = g_gx + ((size_t)dir * 512 + t * 16 + b) * 2048;
        float v[4];
#pragma unroll
        for (int g2 = 0; g2 < 4; g2++) {
            int slot = ((g2 * 8 + hloc) << 4) + b;
            float sum = 0.f;
#pragma unroll
            for (int q = 0; q < 16; q++) sum += sbuf[(q << 9) + slot];
            v[g2] = sum + gx[g2 * 512 + h0 + hloc];
        }
        float i_ = 1.f / (1.f + expf(-v[0]));
        float f_ = 1.f / (1.f + expf(-v[1]));
        float gg = tanhf(v[2]);
        float o_ = 1.f / (1.f + expf(-v[3]));
        int hh = h0 + hloc;
        int ci = dir * 8192 + hh * 16 + b;
        float c = f_ * g_cT[ci] + i_ * gg;
        g_cT[ci] = c;
        float hn = o_ * tanhf(c);
        g_hT[(s + 1) & 1][ci] = hn;
        g_hseq[(t * 16 + b) * 1024 + dir * 512 + hh] = hn;
    }
}

// ---------------- attention (validated R12) ----------------
__global__ __launch_bounds__(256) void k_att_scores(
    const float* __restrict__ w_att, const float* __restrict__ b_att)
{
    __shared__ float hm[4][512];
    __shared__ float wv[512];
    int b = blockIdx.x & 15, tg = blockIdx.x >> 4;
    int tid = threadIdx.x;
    wv[tid] = w_att[tid];
    wv[tid + 256] = w_att[tid + 256];
#pragma unroll
    for (int t4 = 0; t4 < 4; t4++) {
        int row = (tg * 4 + t4) * 16 + b;
        hm[t4][tid] = g_hemA[row * 512 + tid];
        hm[t4][tid + 256] = g_hemA[row * 512 + tid + 256];
    }
    __syncthreads();
    int lane = tid & 31, wrp = tid >> 5;
    float batt = b_att[0];
    const float* xb = g_xt + (size_t)b * 256 * 512;
    for (int hw = wrp; hw < 256; hw += 8) {
        const float* xr = xb + hw * 512;
        float s[4] = {0.f, 0.f, 0.f, 0.f};
        for (int e = lane; e < 512; e += 32) {
            float xv = xr[e], we = wv[e];
#pragma unroll
            for (int t4 = 0; t4 < 4; t4++) s[t4] += we * tanh_fast(xv + hm[t4][e]);
        }
#pragma unroll
        for (int o = 16; o; o >>= 1)
#pragma unroll
            for (int t4 = 0; t4 < 4; t4++) s[t4] += __shfl_xor_sync(0xffffffffu, s[t4], o);
        if (lane == 0)
#pragma unroll
            for (int t4 = 0; t4 < 4; t4++)
                g_sc[((tg * 4 + t4) * 16 + b) * 256 + hw] = s[t4] + batt;
    }
}

__global__ __launch_bounds__(256) void k_att_soft() {
    __shared__ float red[256];
    int r = blockIdx.x;
    int tid = threadIdx.x;
    float sv = g_sc[r * 256 + tid];
    red[tid] = sv;
    __syncthreads();
    for (int st = 128; st; st >>= 1) {
        if (tid < st) red[tid] = fmaxf(red[tid], red[tid + st]);
        __syncthreads();
    }
    float mx = red[0];
    __syncthreads();
    float e = expf(sv - mx);
    red[tid] = e;
    __syncthreads();
    for (int st = 128; st; st >>= 1) {
        if (tid < st) red[tid] += red[tid + st];
        __syncthreads();
    }
    g_alpha[r * 256 + tid] = e / red[0];
}

__global__ __launch_bounds__(256) void k_att_wsum(float* __restrict__ out) {
    __shared__ float al[4][256];
    int b = blockIdx.x & 15, tg = blockIdx.x >> 4;
    int tid = threadIdx.x;
#pragma unroll
    for (int t4 = 0; t4 < 4; t4++)
        al[t4][tid] = g_alpha[((tg * 4 + t4) * 16 + b) * 256 + tid];
    __syncthreads();
    const float* xb = g_xt + (size_t)b * 256 * 512;
    float a0[4] = {0.f, 0.f, 0.f, 0.f};
    float a1[4] = {0.f, 0.f, 0.f, 0.f};
    for (int hw = 0; hw < 256; hw++) {
        float x0 = xb[hw * 512 + tid];
        float x1 = xb[hw * 512 + tid + 256];
#pragma unroll
        for (int t4 = 0; t4 < 4; t4++) {
            float av = al[t4][hw];
            a0[t4] += av * x0;
            a1[t4] += av * x1;
        }
    }
#pragma unroll
    for (int t4 = 0; t4 < 4; t4++) {
        float* orow = out + (size_t)((b << 5) + tg * 4 + t4) * 1024 + 512;
        orow[tid] = a0[t4];
        orow[tid + 256] = a1[t4];
    }
}

// ---------------- launch ----------------
extern "C" void kernel_launch(void* const* d_in, const int* in_sizes, int n_in,
                              void* d_out, int out_size) {
    const float* hidden_en = (const float*)d_in[0];
    const float* conv_f = (const float*)d_in[1];
    const float* W_ih_f = (const float*)d_in[2];
    const float* W_hh_f = (const float*)d_in[3];
    const float* b_ih_f = (const float*)d_in[4];
    const float* b_hh_f = (const float*)d_in[5];
    const float* W_ih_b = (const float*)d_in[6];
    const float* W_hh_b = (const float*)d_in[7];
    const float* b_ih_b = (const float*)d_in[8];
    const float* b_hh_b = (const float*)d_in[9];
    const float* W_dec = (const float*)d_in[10];
    const float* b_dec = (const float*)d_in[11];
    const float* W_em = (const float*)d_in[12];
    const float* b_em = (const float*)d_in[13];
    const float* W_hem = (const float*)d_in[14];
    const float* b_hem = (const float*)d_in[15];
    const float* w_att = (const float*)d_in[16];
    const float* b_att = (const float*)d_in[17];
    float* out = (float*)d_out;

#define SYM(p, s) void* p; cudaGetSymbolAddress(&p, s)
    SYM(p_gx, g_gx); SYM(p_xt, g_xt); SYM(p_hseq, g_hseq); SYM(p_hem, g_hemA);
    SYM(p_col2, g_col2); SYM(p_wem2, g_wem2); SYM(p_en2, g_en2);
    SYM(p_wf2, g_wihf2); SYM(p_wb2, g_wihb2);
    SYM(p_wd2, g_wdec2); SYM(p_wh2, g_whem2);
    SYM(p_hs2, g_hseq2); SYM(p_hd2, g_hde2);

    const int SMB = 6 * 10240;   // 3-stage A+B
    cudaFuncSetAttribute(k_mma_gemm, cudaFuncAttributeMaxDynamicSharedMemorySize, SMB);

    // launches 1-3, then conv GEMM as launch #4 (ncu profiles launch #4)
    k_zero<<<64, 256>>>();
    k_im2col2<<<(4096 * 4608) / 256, 256>>>(conv_f);
    k_cvt2<<<(512 * 4608) / 256, 256>>>(W_em, (bf16*)p_wem2, 4608, 512 * 4608);
    // launch 4: conv GEMM -> g_xt (M=4096, N=512, K=4608)
    k_mma_gemm<<<dim3(4, 32), 256, SMB>>>((bf16*)p_col2, (bf16*)p_wem2, b_em, nullptr,
                                          (float*)p_xt, nullptr, 0, nullptr, 512, 4608);
    // remaining converts
    k_cvt2<<<(512 * 512) / 256, 256>>>(hidden_en, (bf16*)p_en2, 512, 512 * 512);
    k_cvt2<<<(2048 * 512) / 256, 256>>>(W_ih_f, (bf16*)p_wf2, 512, 2048 * 512);
    k_cvt2<<<(2048 * 512) / 256, 256>>>(W_ih_b, (bf16*)p_wb2, 512, 2048 * 512);
    k_cvt2<<<(512 * 1024) / 256, 256>>>(W_dec, (bf16*)p_wd2, 1024, 512 * 1024);
    k_cvt2<<<(512 * 512) / 256, 256>>>(W_hem, (bf16*)p_wh2, 512, 512 * 512);

    // input projections (M=512, N=2048, K=512)
    k_mma_gemm<<<dim3(16, 4), 256, SMB>>>((bf16*)p_en2, (bf16*)p_wf2, b_ih_f, b_hh_f,
                                          (float*)p_gx, nullptr, 0, nullptr, 2048, 512);
    k_mma_gemm<<<dim3(16, 4), 256, SMB>>>((bf16*)p_en2, (bf16*)p_wb2, b_ih_b, b_hh_b,
                                          (float*)p_gx + 512 * 2048, nullptr, 0, nullptr, 2048, 512);

    // bidirectional LSTM recurrence, 128 CTAs per step
    for (int s = 0; s < 32; s++) k_lstm_step<<<128, 256>>>(W_hh_f, W_hh_b, s);

    k_cvt2<<<(512 * 1024) / 256, 256>>>((float*)p_hseq, (bf16*)p_hs2, 1024, 512 * 1024);
    // dec (M=512, N=512, K=1024): scatter hidden_de into out + [hi|lo] hde
    k_mma_gemm<<<dim3(4, 4), 256, SMB>>>((bf16*)p_hs2, (bf16*)p_wd2, b_dec, nullptr,
                                         nullptr, (bf16*)p_hd2, 512, out, 512, 1024);
    // hem (M=512, N=512, K=512)
    k_mma_gemm<<<dim3(4, 4), 256, SMB>>>((bf16*)p_hd2, (bf16*)p_wh2, b_hem, nullptr,
                                         (float*)p_hem, nullptr, 0, nullptr, 512, 512);

    // attention
    k_att_scores<<<128, 256>>>(w_att, b_att);
    k_att_soft<<<512, 256>>>();
    k_att_wsum<<<128, 256>>>(out);
}

// round 17
// speedup vs baseline: 1.6920x; 1.0972x over previous
#include <cuda_runtime.h>
#include <cuda_bf16.h>
#include <math.h>
#include <stdint.h>

typedef __nv_bfloat16 bf16;

// ---------------- scratch ----------------
__device__ float g_hT[2][16384];
__device__ float g_cT[16384];
__device__ float g_hseq[512 * 1024];
__device__ float g_gx[2 * 512 * 2048];
__device__ float g_hemA[512 * 512];
__device__ float g_xt[4096 * 512];
__device__ float g_sc[512 * 256];
__device__ float g_alpha[512 * 256];
__device__ bf16 g_col2[4096u * 9216u];          // [hi(4608) | lo(4608)]
__device__ bf16 g_wem2[512 * 9216];
__device__ bf16 g_en2[512 * 1024];
__device__ bf16 g_wihf2[2048 * 1024], g_wihb2[2048 * 1024];
__device__ bf16 g_wdec2[512 * 2048];
__device__ bf16 g_whem2[512 * 1024];
__device__ bf16 g_hseq2[512 * 2048];
__device__ bf16 g_hde2[512 * 1024];

// ---------------- helpers ----------------
__device__ __forceinline__ void fma2(unsigned long long& d, unsigned long long a, unsigned long long b) {
    asm("fma.rn.f32x2 %0, %1, %2, %0;" : "+l"(d) : "l"(a), "l"(b));
}
__device__ __forceinline__ float2 upk(unsigned long long v) {
    float2 f;
    asm("mov.b64 {%0, %1}, %2;" : "=f"(f.x), "=f"(f.y) : "l"(v));
    return f;
}
__device__ __forceinline__ float tanh_fast(float x) {
    float y;
    asm("tanh.approx.f32 %0, %1;" : "=f"(y) : "f"(x));
    return y;
}
__device__ __forceinline__ uint32_t smem_u32(const void* p) {
    uint32_t a;
    asm("{ .reg .u64 t; cvta.to.shared.u64 t, %1; cvt.u32.u64 %0, t; }" : "=r"(a) : "l"(p));
    return a;
}
__device__ __forceinline__ void ldsm4(uint32_t& r0, uint32_t& r1, uint32_t& r2, uint32_t& r3,
                                      uint32_t addr) {
    asm volatile("ldmatrix.sync.aligned.m8n8.x4.shared.b16 {%0,%1,%2,%3}, [%4];"
                 : "=r"(r0), "=r"(r1), "=r"(r2), "=r"(r3) : "r"(addr));
}

// ---------------- init & converts ----------------
__global__ void k_zero() {
    int i = blockIdx.x * 256 + threadIdx.x;
    g_hT[0][i] = 0.f;
    g_cT[i] = 0.f;
}
__global__ void k_cvt2(const float* __restrict__ s, bf16* __restrict__ d, int K, int n) {
    int i = blockIdx.x * 256 + threadIdx.x;
    if (i >= n) return;
    int m = i / K, k = i % K;
    float v = s[i];
    bf16 h = __float2bfloat16(v);
    bf16 l = __float2bfloat16(v - __bfloat162float(h));
    size_t base = (size_t)m * 2 * K;
    d[base + k] = h;
    d[base + K + k] = l;
}
__global__ void k_im2col2(const float* __restrict__ cf) {
    int idx = blockIdx.x * 256 + threadIdx.x;   // < 4096*4608
    int k = idx % 4608, m = idx / 4608;
    int kw = k % 3, kh = (k / 3) % 3, c = k / 9;
    int w = m & 31, h = (m >> 5) & 7, b = m >> 8;
    int ih = h + kh - 1, iw = w + kw - 1;
    float v = 0.f;
    if (ih >= 0 && ih < 8 && iw >= 0 && iw < 32) v = cf[((b * 512 + c) * 8 + ih) * 32 + iw];
    bf16 hv = __float2bfloat16(v);
    size_t base = (size_t)m * 9216;
    g_col2[base + k] = hv;
    g_col2[base + 4608 + k] = __float2bfloat16(v - __bfloat162float(hv));
}

// ---------------- HMMA bf16 NT GEMM: 128x64 tile, ldmatrix + 3-stage cp.async ----
#define PAD 40
#define TSZA 10240u   // 128 rows * 40 elem * 2B
#define TSZBB 5120u   // 64 rows * 40 elem * 2B
__device__ __forceinline__ void ld_chunkA(uint32_t ds, const bf16* __restrict__ src,
                                          int row0, int rs, int koff, int tid) {
#pragma unroll
    for (int j = 0; j < 2; j++) {
        int ch = tid + (j << 8);
        int row = ch >> 2, c = ch & 3;
        const void* g = src + (size_t)(row0 + row) * rs + koff + (c << 3);
        uint32_t d = ds + (row * PAD + (c << 3)) * 2;
        asm volatile("cp.async.ca.shared.global [%0], [%1], 16;" :: "r"(d), "l"(g) : "memory");
    }
}
__device__ __forceinline__ void ld_chunkB(uint32_t ds, const bf16* __restrict__ src,
                                          int row0, int rs, int koff, int tid) {
    int row = tid >> 2, c = tid & 3;            // 64 rows x 4 chunks = 256 threads
    const void* g = src + (size_t)(row0 + row) * rs + koff + (c << 3);
    uint32_t d = ds + (row * PAD + (c << 3)) * 2;
    asm volatile("cp.async.ca.shared.global [%0], [%1], 16;" :: "r"(d), "l"(g) : "memory");
}

__global__ __launch_bounds__(256) void k_mma_gemm(
    const bf16* __restrict__ A2, const bf16* __restrict__ B2,
    const float* __restrict__ bias, const float* __restrict__ bias2,
    float* __restrict__ Cf, bf16* __restrict__ C2, int C2K,
    float* __restrict__ Cscat, int N, int K)
{
    extern __shared__ __align__(16) char dsm[];
    uint32_t asb = smem_u32(dsm);            // A stages at asb + st*TSZA
    uint32_t bsb = asb + 3 * TSZA;           // B stages at bsb + st*TSZBB
    int tid = threadIdx.x, lane = tid & 31, wid = tid >> 5;
    int g = lane >> 2, t2 = (lane & 3) << 1;
    int bm = blockIdx.y << 7, bn = blockIdx.x << 6;
    int wm = (wid >> 1) << 5, wn = (wid & 1) << 5;     // warp tile 32x32
    int rs = K << 1;
    int KC = K >> 5, S = KC * 3;

    int lr8 = lane & 7, half = (lane >> 3) & 1, quad = lane >> 4;
    uint32_t aoffB[2], boffB[2];
#pragma unroll
    for (int mt = 0; mt < 2; mt++)
        aoffB[mt] = ((wm + (mt << 4) + lr8 + (half << 3)) * PAD + (quad << 3)) * 2;
#pragma unroll
    for (int np = 0; np < 2; np++)
        boffB[np] = ((wn + (np << 4) + (quad << 3) + lr8) * PAD + (half << 3)) * 2;

    float acc[2][4][4];
#pragma unroll
    for (int mt = 0; mt < 2; mt++)
#pragma unroll
        for (int nt = 0; nt < 4; nt++)
#pragma unroll
            for (int q = 0; q < 4; q++) acc[mt][nt][q] = 0.f;

    // prologue: stages 0 and 1
#pragma unroll
    for (int st = 0; st < 2; st++) {
        int p = st / KC, cc = st - p * KC;
        int ao = ((p == 2) ? K : 0) + (cc << 5);
        int bo = ((p == 1) ? K : 0) + (cc << 5);
        ld_chunkA(asb + st * TSZA, A2, bm, rs, ao, tid);
        ld_chunkB(bsb + st * TSZBB, B2, bn, rs, bo, tid);
        asm volatile("cp.async.commit_group;" ::: "memory");
    }

    for (int s = 0; s < S; s++) {
        if (s == S - 1) asm volatile("cp.async.wait_group 0;" ::: "memory");
        else            asm volatile("cp.async.wait_group 1;" ::: "memory");
        __syncthreads();
        if (s + 2 < S) {
            int st = s + 2, bufn = st % 3;
            int p = st / KC, cc = st - p * KC;
            int ao = ((p == 2) ? K : 0) + (cc << 5);
            int bo = ((p == 1) ? K : 0) + (cc << 5);
            ld_chunkA(asb + bufn * TSZA, A2, bm, rs, ao, tid);
            ld_chunkB(bsb + bufn * TSZBB, B2, bn, rs, bo, tid);
            asm volatile("cp.async.commit_group;" ::: "memory");
        }
        uint32_t ab = asb + (uint32_t)(s % 3) * TSZA;
        uint32_t bb = bsb + (uint32_t)(s % 3) * TSZBB;
#pragma unroll
        for (int kk = 0; kk < 2; kk++) {
            uint32_t kby = (uint32_t)(kk << 5);   // 16 elems * 2B
            uint32_t a[2][4], b[4][2];
#pragma unroll
            for (int mt = 0; mt < 2; mt++)
                ldsm4(a[mt][0], a[mt][1], a[mt][2], a[mt][3], ab + aoffB[mt] + kby);
#pragma unroll
            for (int np = 0; np < 2; np++)
                ldsm4(b[2 * np][0], b[2 * np][1], b[2 * np + 1][0], b[2 * np + 1][1],
                      bb + boffB[np] + kby);
#pragma unroll
            for (int mt = 0; mt < 2; mt++)
#pragma unroll
                for (int nt = 0; nt < 4; nt++)
                    asm volatile(
                        "mma.sync.aligned.m16n8k16.row.col.f32.bf16.bf16.f32 "
                        "{%0,%1,%2,%3},{%4,%5,%6,%7},{%8,%9},{%0,%1,%2,%3};"
                        : "+f"(acc[mt][nt][0]), "+f"(acc[mt][nt][1]),
                          "+f"(acc[mt][nt][2]), "+f"(acc[mt][nt][3])
                        : "r"(a[mt][0]), "r"(a[mt][1]), "r"(a[mt][2]), "r"(a[mt][3]),
                          "r"(b[nt][0]), "r"(b[nt][1]));
        }
    }
#pragma unroll
    for (int mt = 0; mt < 2; mt++)
#pragma unroll
        for (int nt = 0; nt < 4; nt++) {
            int r0 = bm + wm + (mt << 4) + g;
            int c0 = bn + wn + (nt << 3) + t2;
            float bv0 = bias[c0] + (bias2 ? bias2[c0] : 0.f);
            float bv1 = bias[c0 + 1] + (bias2 ? bias2[c0 + 1] : 0.f);
            float v[4] = {acc[mt][nt][0] + bv0, acc[mt][nt][1] + bv1,
                          acc[mt][nt][2] + bv0, acc[mt][nt][3] + bv1};
            int rr[4] = {r0, r0, r0 + 8, r0 + 8};
            int cc[4] = {c0, c0 + 1, c0, c0 + 1};
#pragma unroll
            for (int q = 0; q < 4; q++) {
                int m = rr[q], n = cc[q];
                float x = v[q];
                if (Cf) Cf[(size_t)m * N + n] = x;
                if (C2) {
                    bf16 h = __float2bfloat16(x);
                    size_t base = (size_t)m * 2 * C2K;
                    C2[base + n] = h;
                    C2[base + C2K + n] = __float2bfloat16(x - __bfloat162float(h));
                }
                if (Cscat) {
                    int t = m >> 4, bb_ = m & 15;
                    Cscat[((bb_ << 5) + t) * 1024 + n] = x;
                }
            }
        }
}

// ---------------- LSTM step, 128 CTAs (h-tile 8, 16-way k-split) ----------------
__global__ __launch_bounds__(256) void k_lstm_step(
    const float* __restrict__ Whh_f, const float* __restrict__ Whh_b, int s)
{
    __shared__ float sbuf[8192];
    int dir = blockIdx.x & 1;
    int h0 = (blockIdx.x >> 1) << 3;              // 64 tiles of 8 h
    int t = dir ? (31 - s) : s;
    const float* __restrict__ Whh = dir ? Whh_b : Whh_f;
    int tid = threadIdx.x;
    {
        const float4* hp4 = (const float4*)(g_hT[s & 1] + dir * 8192);
        float4* sb4 = (float4*)sbuf;
#pragma unroll
        for (int i = 0; i < 8; i++) sb4[tid + i * 256] = hp4[tid + i * 256];
    }
    __syncthreads();
    int kq = tid >> 4;                 // 16 k-splits of 32
    int gate = (tid >> 2) & 3;
    int hp = tid & 3;                  // 2 h each
    int h = h0 + (hp << 1);
    const float* wr0 = Whh + (size_t)(gate * 512 + h) * 512 + (kq << 5);
    const float* wr1 = wr0 + 512;
    unsigned long long acc[2][8];
#pragma unroll
    for (int p = 0; p < 2; p++)
#pragma unroll
        for (int j = 0; j < 8; j++) acc[p][j] = 0ull;

    for (int k4 = 0; k4 < 32; k4 += 4) {
        float4 wa = *(const float4*)(wr0 + k4);
        float4 wb = *(const float4*)(wr1 + k4);
        float wav[4] = {wa.x, wa.y, wa.z, wa.w};
        float wbv[4] = {wb.x, wb.y, wb.z, wb.w};
#pragma unroll
        for (int j = 0; j < 4; j++) {
            int k = (kq << 5) + k4 + j;
            unsigned long long w2a, w2b;
            asm("mov.b64 %0, {%1, %1};" : "=l"(w2a) : "f"(wav[j]));
            asm("mov.b64 %0, {%1, %1};" : "=l"(w2b) : "f"(wbv[j]));
            const ulonglong2* hb = (const ulonglong2*)&sbuf[k << 4];
            ulonglong2 q0 = hb[0], q1 = hb[1], q2 = hb[2], q3 = hb[3];
            fma2(acc[0][0], w2a, q0.x); fma2(acc[0][1], w2a, q0.y);
            fma2(acc[0][2], w2a, q1.x); fma2(acc[0][3], w2a, q1.y);
            fma2(acc[0][4], w2a, q2.x); fma2(acc[0][5], w2a, q2.y);
            fma2(acc[0][6], w2a, q3.x); fma2(acc[0][7], w2a, q3.y);
            fma2(acc[1][0], w2b, q0.x); fma2(acc[1][1], w2b, q0.y);
            fma2(acc[1][2], w2b, q1.x); fma2(acc[1][3], w2b, q1.y);
            fma2(acc[1][4], w2b, q2.x); fma2(acc[1][5], w2b, q2.y);
            fma2(acc[1][6], w2b, q3.x); fma2(acc[1][7], w2b, q3.y);
        }
    }
    __syncthreads();   // done reading h; reuse sbuf for partials
#pragma unroll
    for (int p = 0; p < 2; p++)
#pragma unroll
        for (int j = 0; j < 8; j++) {
            float2 v = upk(acc[p][j]);
            int base = (kq << 9) + ((gate * 8 + (hp << 1) + p) << 4) + (j << 1);
            sbuf[base] = v.x;
            sbuf[base + 1] = v.y;
        }
    __syncthreads();
    if (tid < 128) {
        int hloc = tid >> 4, b = tid & 15;
        const float* gx = g_gx + ((size_t)dir * 512 + t * 16 + b) * 2048;
        float v[4];
#pragma unroll
        for (int g2 = 0; g2 < 4; g2++) {
            int slot = ((g2 * 8 + hloc) << 4) + b;
            float sum = 0.f;
#pragma unroll
            for (int q = 0; q < 16; q++) sum += sbuf[(q << 9) + slot];
            v[g2] = sum + gx[g2 * 512 + h0 + hloc];
        }
        float i_ = 1.f / (1.f + expf(-v[0]));
        float f_ = 1.f / (1.f + expf(-v[1]));
        float gg = tanhf(v[2]);
        float o_ = 1.f / (1.f + expf(-v[3]));
        int hh = h0 + hloc;
        int ci = dir * 8192 + hh * 16 + b;
        float c = f_ * g_cT[ci] + i_ * gg;
        g_cT[ci] = c;
        float hn = o_ * tanhf(c);
        g_hT[(s + 1) & 1][ci] = hn;
        g_hseq[(t * 16 + b) * 1024 + dir * 512 + hh] = hn;
    }
}

// ---------------- attention (validated R12) ----------------
__global__ __launch_bounds__(256) void k_att_scores(
    const float* __restrict__ w_att, const float* __restrict__ b_att)
{
    __shared__ float hm[4][512];
    __shared__ float wv[512];
    int b = blockIdx.x & 15, tg = blockIdx.x >> 4;
    int tid = threadIdx.x;
    wv[tid] = w_att[tid];
    wv[tid + 256] = w_att[tid + 256];
#pragma unroll
    for (int t4 = 0; t4 < 4; t4++) {
        int row = (tg * 4 + t4) * 16 + b;
        hm[t4][tid] = g_hemA[row * 512 + tid];
        hm[t4][tid + 256] = g_hemA[row * 512 + tid + 256];
    }
    __syncthreads();
    int lane = tid & 31, wrp = tid >> 5;
    float batt = b_att[0];
    const float* xb = g_xt + (size_t)b * 256 * 512;
    for (int hw = wrp; hw < 256; hw += 8) {
        const float* xr = xb + hw * 512;
        float s[4] = {0.f, 0.f, 0.f, 0.f};
        for (int e = lane; e < 512; e += 32) {
            float xv = xr[e], we = wv[e];
#pragma unroll
            for (int t4 = 0; t4 < 4; t4++) s[t4] += we * tanh_fast(xv + hm[t4][e]);
        }
#pragma unroll
        for (int o = 16; o; o >>= 1)
#pragma unroll
            for (int t4 = 0; t4 < 4; t4++) s[t4] += __shfl_xor_sync(0xffffffffu, s[t4], o);
        if (lane == 0)
#pragma unroll
            for (int t4 = 0; t4 < 4; t4++)
                g_sc[((tg * 4 + t4) * 16 + b) * 256 + hw] = s[t4] + batt;
    }
}

__global__ __launch_bounds__(256) void k_att_soft() {
    __shared__ float red[256];
    int r = blockIdx.x;
    int tid = threadIdx.x;
    float sv = g_sc[r * 256 + tid];
    red[tid] = sv;
    __syncthreads();
    for (int st = 128; st; st >>= 1) {
        if (tid < st) red[tid] = fmaxf(red[tid], red[tid + st]);
        __syncthreads();
    }
    float mx = red[0];
    __syncthreads();
    float e = expf(sv - mx);
    red[tid] = e;
    __syncthreads();
    for (int st = 128; st; st >>= 1) {
        if (tid < st) red[tid] += red[tid + st];
        __syncthreads();
    }
    g_alpha[r * 256 + tid] = e / red[0];
}

__global__ __launch_bounds__(256) void k_att_wsum(float* __restrict__ out) {
    __shared__ float al[4][256];
    int b = blockIdx.x & 15, tg = blockIdx.x >> 4;
    int tid = threadIdx.x;
#pragma unroll
    for (int t4 = 0; t4 < 4; t4++)
        al[t4][tid] = g_alpha[((tg * 4 + t4) * 16 + b) * 256 + tid];
    __syncthreads();
    const float* xb = g_xt + (size_t)b * 256 * 512;
    float a0[4] = {0.f, 0.f, 0.f, 0.f};
    float a1[4] = {0.f, 0.f, 0.f, 0.f};
    for (int hw = 0; hw < 256; hw++) {
        float x0 = xb[hw * 512 + tid];
        float x1 = xb[hw * 512 + tid + 256];
#pragma unroll
        for (int t4 = 0; t4 < 4; t4++) {
            float av = al[t4][hw];
            a0[t4] += av * x0;
            a1[t4] += av * x1;
        }
    }
#pragma unroll
    for (int t4 = 0; t4 < 4; t4++) {
        float* orow = out + (size_t)((b << 5) + tg * 4 + t4) * 1024 + 512;
        orow[tid] = a0[t4];
        orow[tid + 256] = a1[t4];
    }
}

// ---------------- launch ----------------
extern "C" void kernel_launch(void* const* d_in, const int* in_sizes, int n_in,
                              void* d_out, int out_size) {
    const float* hidden_en = (const float*)d_in[0];
    const float* conv_f = (const float*)d_in[1];
    const float* W_ih_f = (const float*)d_in[2];
    const float* W_hh_f = (const float*)d_in[3];
    const float* b_ih_f = (const float*)d_in[4];
    const float* b_hh_f = (const float*)d_in[5];
    const float* W_ih_b = (const float*)d_in[6];
    const float* W_hh_b = (const float*)d_in[7];
    const float* b_ih_b = (const float*)d_in[8];
    const float* b_hh_b = (const float*)d_in[9];
    const float* W_dec = (const float*)d_in[10];
    const float* b_dec = (const float*)d_in[11];
    const float* W_em = (const float*)d_in[12];
    const float* b_em = (const float*)d_in[13];
    const float* W_hem = (const float*)d_in[14];
    const float* b_hem = (const float*)d_in[15];
    const float* w_att = (const float*)d_in[16];
    const float* b_att = (const float*)d_in[17];
    float* out = (float*)d_out;

#define SYM(p, s) void* p; cudaGetSymbolAddress(&p, s)
    SYM(p_gx, g_gx); SYM(p_xt, g_xt); SYM(p_hseq, g_hseq); SYM(p_hem, g_hemA);
    SYM(p_col2, g_col2); SYM(p_wem2, g_wem2); SYM(p_en2, g_en2);
    SYM(p_wf2, g_wihf2); SYM(p_wb2, g_wihb2);
    SYM(p_wd2, g_wdec2); SYM(p_wh2, g_whem2);
    SYM(p_hs2, g_hseq2); SYM(p_hd2, g_hde2);

    const int SMB = 3 * 10240 + 3 * 5120;   // 3-stage A(128) + B(64)
    cudaFuncSetAttribute(k_mma_gemm, cudaFuncAttributeMaxDynamicSharedMemorySize, SMB);

    // launches 1-3, then conv GEMM as launch #4 (ncu profiles launch #4)
    k_zero<<<64, 256>>>();
    k_im2col2<<<(4096 * 4608) / 256, 256>>>(conv_f);
    k_cvt2<<<(512 * 4608) / 256, 256>>>(W_em, (bf16*)p_wem2, 4608, 512 * 4608);
    // launch 4: conv GEMM -> g_xt (M=4096, N=512, K=4608), 256 CTAs
    k_mma_gemm<<<dim3(8, 32), 256, SMB>>>((bf16*)p_col2, (bf16*)p_wem2, b_em, nullptr,
                                          (float*)p_xt, nullptr, 0, nullptr, 512, 4608);
    // remaining converts
    k_cvt2<<<(512 * 512) / 256, 256>>>(hidden_en, (bf16*)p_en2, 512, 512 * 512);
    k_cvt2<<<(2048 * 512) / 256, 256>>>(W_ih_f, (bf16*)p_wf2, 512, 2048 * 512);
    k_cvt2<<<(2048 * 512) / 256, 256>>>(W_ih_b, (bf16*)p_wb2, 512, 2048 * 512);
    k_cvt2<<<(512 * 1024) / 256, 256>>>(W_dec, (bf16*)p_wd2, 1024, 512 * 1024);
    k_cvt2<<<(512 * 512) / 256, 256>>>(W_hem, (bf16*)p_wh2, 512, 512 * 512);

    // input projections (M=512, N=2048, K=512), 128 CTAs each
    k_mma_gemm<<<dim3(32, 4), 256, SMB>>>((bf16*)p_en2, (bf16*)p_wf2, b_ih_f, b_hh_f,
                                          (float*)p_gx, nullptr, 0, nullptr, 2048, 512);
    k_mma_gemm<<<dim3(32, 4), 256, SMB>>>((bf16*)p_en2, (bf16*)p_wb2, b_ih_b, b_hh_b,
                                          (float*)p_gx + 512 * 2048, nullptr, 0, nullptr, 2048, 512);

    // bidirectional LSTM recurrence, 128 CTAs per step
    for (int s = 0; s < 32; s++) k_lstm_step<<<128, 256>>>(W_hh_f, W_hh_b, s);

    k_cvt2<<<(512 * 1024) / 256, 256>>>((float*)p_hseq, (bf16*)p_hs2, 1024, 512 * 1024);
    // dec (M=512, N=512, K=1024): scatter hidden_de into out + [hi|lo] hde
    k_mma_gemm<<<dim3(8, 4), 256, SMB>>>((bf16*)p_hs2, (bf16*)p_wd2, b_dec, nullptr,
                                         nullptr, (bf16*)p_hd2, 512, out, 512, 1024);
    // hem (M=512, N=512, K=512)
    k_mma_gemm<<<dim3(8, 4), 256, SMB>>>((bf16*)p_hd2, (bf16*)p_wh2, b_hem, nullptr,
                                         (float*)p_hem, nullptr, 0, nullptr, 512, 512);

    // attention
    k_att_scores<<<128, 256>>>(w_att, b_att);
    k_att_soft<<<512, 256>>>();
    k_att_wsum<<<128, 256>>>(out);
}